// round 8
// baseline (speedup 1.0000x reference)
#include <cuda_runtime.h>
#include <cuda_bf16.h>
#include <mma.h>

using namespace nvcuda;

#define N_NODES 262144
#define N_EDGES 1048576
#define N_GRAPHS 8192
#define H 128
#define H2 256
#define LAYERS 4
#define FA 9
#define VA 64
#define FB 3
#define VB 8

// ---------------- scratch ----------------------------------------------------
__device__ float g_h[(size_t)N_NODES * H];
__device__ float g_agg[(size_t)N_NODES * H];
__device__ float g_t[(size_t)N_NODES * H2];
__device__ float g_vn[(size_t)N_GRAPHS * H];
__device__ float g_pooled[(size_t)N_GRAPHS * H2];
// bf16 3-way split weights [K][N] for W1, W2, V2 (V1 stays fp32)
#define WT_L (32768 + 32768 + 32768)   // 98304 per layer
__device__ __nv_bfloat16 g_w0[(size_t)LAYERS * WT_L];
__device__ __nv_bfloat16 g_w1[(size_t)LAYERS * WT_L];
__device__ __nv_bfloat16 g_w2[(size_t)LAYERS * WT_L];

// ---- elementwise bf16x3 weight split -----------------------------------------
__global__ void wconv3_kernel(const float* __restrict__ W,
                              __nv_bfloat16* __restrict__ W0,
                              __nv_bfloat16* __restrict__ W1,
                              __nv_bfloat16* __restrict__ W2, int total) {
    int idx = blockIdx.x * blockDim.x + threadIdx.x;
    if (idx >= total) return;
    float w = W[idx];
    __nv_bfloat16 b0 = __float2bfloat16(w);
    float r1 = w - __bfloat162float(b0);
    __nv_bfloat16 b1 = __float2bfloat16(r1);
    float r2 = r1 - __bfloat162float(b1);
    W0[idx] = b0;
    W1[idx] = b1;
    W2[idx] = __float2bfloat16(r2);
}

// ---------------- atom encoder ------------------------------------------------
__global__ void atom_kernel(const int* __restrict__ x,
                            const float* __restrict__ emb,
                            float* __restrict__ h) {
    int idx = blockIdx.x * blockDim.x + threadIdx.x;
    int n = idx >> 5;
    int c = (idx & 31) << 2;
    float4 acc = make_float4(0.f, 0.f, 0.f, 0.f);
#pragma unroll
    for (int f = 0; f < FA; f++) {
        int v = x[n * FA + f];
        float4 e = *(const float4*)(emb + ((size_t)(f * VA + v) * H) + c);
        acc.x += e.x; acc.y += e.y; acc.z += e.z; acc.w += e.w;
    }
    *(float4*)(h + (size_t)n * H + c) = acc;
}

// ---------------- vn init ------------------------------------------------------
__global__ void vninit_kernel(const float* __restrict__ vn_emb,
                              float* __restrict__ vn) {
    int idx = blockIdx.x * blockDim.x + threadIdx.x;
    int g = idx >> 5;
    int c = (idx & 31) << 2;
    *(float4*)(vn + (size_t)g * H + c) = *(const float4*)(vn_emb + c);
}

// ---------------- h += vn[batch]; agg = 0 --------------------------------------
__global__ void addvn_kernel(float* __restrict__ h,
                             const float* __restrict__ vn,
                             const int* __restrict__ batch,
                             float* __restrict__ agg) {
    int idx = blockIdx.x * blockDim.x + threadIdx.x;
    int n = idx >> 5;
    int c = (idx & 31) << 2;
    int g = batch[n];
    float4 hv = *(float4*)(h + (size_t)n * H + c);
    float4 vv = *(const float4*)(vn + (size_t)g * H + c);
    hv.x += vv.x; hv.y += vv.y; hv.z += vv.z; hv.w += vv.w;
    *(float4*)(h + (size_t)n * H + c) = hv;
    *(float4*)(agg + (size_t)n * H + c) = make_float4(0.f, 0.f, 0.f, 0.f);
}

// ---------------- edge message -------------------------------------------------
__global__ void edge_kernel(const int* __restrict__ ei,
                            const int* __restrict__ ea,
                            const float* __restrict__ bond,
                            const float* __restrict__ h,
                            float* __restrict__ agg) {
    __shared__ float tab[FB * VB * H];
    for (int i = threadIdx.x; i < FB * VB * H; i += blockDim.x) tab[i] = bond[i];
    __syncthreads();
    int e = (blockIdx.x * blockDim.x + threadIdx.x) >> 5;
    int lane = threadIdx.x & 31;
    int src = ei[e];
    int dst = ei[N_EDGES + e];
    int a0 = ea[e * 3 + 0], a1 = ea[e * 3 + 1], a2 = ea[e * 3 + 2];
    int c = lane << 2;
    float4 hv = *(const float4*)(h + (size_t)src * H + c);
    float4 e0 = *(const float4*)(tab + (0 * VB + a0) * H + c);
    float4 e1 = *(const float4*)(tab + (1 * VB + a1) * H + c);
    float4 e2 = *(const float4*)(tab + (2 * VB + a2) * H + c);
    float m0 = fmaxf(hv.x + e0.x + e1.x + e2.x, 0.f);
    float m1 = fmaxf(hv.y + e0.y + e1.y + e2.y, 0.f);
    float m2 = fmaxf(hv.z + e0.z + e1.z + e2.z, 0.f);
    float m3 = fmaxf(hv.w + e0.w + e1.w + e2.w, 0.f);
    float* p = agg + (size_t)dst * H + c;
    atomicAdd(p + 0, m0);
    atomicAdd(p + 1, m1);
    atomicAdd(p + 2, m2);
    atomicAdd(p + 3, m3);
}

// ======== PROVEN round-1 SIMT fp32 GEMM (used for vn1 / MODE 2) ===============
template <int MODE_A, bool BN_RELU>
__global__ __launch_bounds__(256) void gemm_simt(
    const float* __restrict__ A, const float* __restrict__ A2,
    const int* __restrict__ batch,
    const float* __restrict__ W, const float* __restrict__ bias,
    const float* __restrict__ bng, const float* __restrict__ bnb,
    const float* __restrict__ bnm, const float* __restrict__ bnv,
    float* __restrict__ C, int M, int K, int Ncol,
    const float* __restrict__ epsp) {
    __shared__ float As[16][64];
    __shared__ float Bs[16][64];
    const int tid = threadIdx.x;
    const int m0 = blockIdx.x * 64;
    const int n0 = blockIdx.y * 64;
    const int tr = tid >> 4;
    const int tc = tid & 15;
    const int am = tid & 63;
    const int ak = (tid >> 6) << 2;
    const int bn = (tid & 15) << 2;
    const int bk = tid >> 4;
    const int grow = m0 + am;
    float c0 = 1.0f;
    if (MODE_A == 1) c0 = 1.0f + __ldg(epsp);
    int bg = 0;
    if (MODE_A == 2) bg = batch[grow];

    float acc[4][4];
#pragma unroll
    for (int i = 0; i < 4; i++)
#pragma unroll
        for (int j = 0; j < 4; j++) acc[i][j] = 0.f;

    for (int k0 = 0; k0 < K; k0 += 16) {
        float4 a4;
        int gk = k0 + ak;
        if (MODE_A == 0) {
            a4 = *(const float4*)(A + (size_t)grow * K + gk);
        } else if (MODE_A == 1) {
            float4 hv = *(const float4*)(A + (size_t)grow * K + gk);
            float4 gv = *(const float4*)(A2 + (size_t)grow * K + gk);
            a4.x = fmaf(c0, hv.x, gv.x);
            a4.y = fmaf(c0, hv.y, gv.y);
            a4.z = fmaf(c0, hv.z, gv.z);
            a4.w = fmaf(c0, hv.w, gv.w);
        } else {
            if (gk < H) a4 = *(const float4*)(A2 + (size_t)bg * H + gk);
            else        a4 = *(const float4*)(A + (size_t)grow * H + (gk - H));
        }
        As[ak + 0][am] = a4.x;
        As[ak + 1][am] = a4.y;
        As[ak + 2][am] = a4.z;
        As[ak + 3][am] = a4.w;
        *(float4*)(&Bs[bk][bn]) =
            *(const float4*)(W + (size_t)(k0 + bk) * Ncol + n0 + bn);
        __syncthreads();
#pragma unroll
        for (int kk = 0; kk < 16; kk++) {
            float ar[4], br[4];
            *(float4*)ar = *(const float4*)(&As[kk][tr << 2]);
            *(float4*)br = *(const float4*)(&Bs[kk][tc << 2]);
#pragma unroll
            for (int i = 0; i < 4; i++)
#pragma unroll
                for (int j = 0; j < 4; j++)
                    acc[i][j] = fmaf(ar[i], br[j], acc[i][j]);
        }
        __syncthreads();
    }

    float sc[4], off[4];
#pragma unroll
    for (int j = 0; j < 4; j++) {
        int col = n0 + (tc << 2) + j;
        if (BN_RELU) {
            float s = __ldg(bng + col) * rsqrtf(__ldg(bnv + col) + 1e-5f);
            sc[j] = s;
            off[j] = (__ldg(bias + col) - __ldg(bnm + col)) * s + __ldg(bnb + col);
        } else {
            sc[j] = 1.0f;
            off[j] = __ldg(bias + col);
        }
    }
#pragma unroll
    for (int i = 0; i < 4; i++) {
        int row = m0 + (tr << 2) + i;
        float4 v;
        float* vp = (float*)&v;
#pragma unroll
        for (int j = 0; j < 4; j++) {
            float y = fmaf(acc[i][j], sc[j], off[j]);
            if (BN_RELU) y = fmaxf(y, 0.0f);
            vp[j] = y;
        }
        *(float4*)(C + (size_t)row * Ncol + n0 + (tc << 2)) = v;
    }
}

// ======== bf16x3 WMMA GEMM (overflow-proof; modes 0 and 1) =====================
// a = a0+a1+a2 (bf16); acc0 = A0@B0; accR = A0@B1+A1@B0+A1@B1+A0@B2+A2@B0.
template <int MODE_A, bool BN_RELU>
__global__ __launch_bounds__(256) void gemm_wmma3(
    const float* __restrict__ A, const float* __restrict__ A2,
    const __nv_bfloat16* __restrict__ W0, const __nv_bfloat16* __restrict__ W1,
    const __nv_bfloat16* __restrict__ W2,
    const float* __restrict__ bias,
    const float* __restrict__ bng, const float* __restrict__ bnb,
    const float* __restrict__ bnm, const float* __restrict__ bnv,
    float* __restrict__ C, int M, int K, int Ncol,
    const float* __restrict__ epsp) {
    __shared__ __nv_bfloat16 A0s[128][16];
    __shared__ __nv_bfloat16 A1s[128][16];
    __shared__ __nv_bfloat16 A2s[128][16];
    __shared__ float Cs[128][64];

    const int tid = threadIdx.x;
    const int wid = tid >> 5;
    const int wm = wid & 3;
    const int wn = wid >> 2;
    const int m0 = blockIdx.x * 128;
    const int n0 = blockIdx.y * 64;

    const int arow = tid >> 1;
    const int akoff = (tid & 1) << 3;
    const int grow = m0 + arow;

    float c0 = 1.0f;
    if (MODE_A == 1) c0 = 1.0f + __ldg(epsp);

    wmma::fragment<wmma::accumulator, 16, 16, 16, float> acc0[2][2], accR[2][2];
#pragma unroll
    for (int mi = 0; mi < 2; mi++)
#pragma unroll
        for (int ni = 0; ni < 2; ni++) {
            wmma::fill_fragment(acc0[mi][ni], 0.0f);
            wmma::fill_fragment(accR[mi][ni], 0.0f);
        }

    for (int k0 = 0; k0 < K; k0 += 16) {
        float v[8];
        {
            int gk = k0 + akoff;
            if (MODE_A == 0) {
                float4 v0 = *(const float4*)(A + (size_t)grow * K + gk);
                float4 v1 = *(const float4*)(A + (size_t)grow * K + gk + 4);
                v[0]=v0.x; v[1]=v0.y; v[2]=v0.z; v[3]=v0.w;
                v[4]=v1.x; v[5]=v1.y; v[6]=v1.z; v[7]=v1.w;
            } else {
                float4 h0 = *(const float4*)(A + (size_t)grow * K + gk);
                float4 h1 = *(const float4*)(A + (size_t)grow * K + gk + 4);
                float4 g0 = *(const float4*)(A2 + (size_t)grow * K + gk);
                float4 g1 = *(const float4*)(A2 + (size_t)grow * K + gk + 4);
                v[0]=fmaf(c0,h0.x,g0.x); v[1]=fmaf(c0,h0.y,g0.y);
                v[2]=fmaf(c0,h0.z,g0.z); v[3]=fmaf(c0,h0.w,g0.w);
                v[4]=fmaf(c0,h1.x,g1.x); v[5]=fmaf(c0,h1.y,g1.y);
                v[6]=fmaf(c0,h1.z,g1.z); v[7]=fmaf(c0,h1.w,g1.w);
            }
        }
        __syncthreads();   // previous slab fully consumed
#pragma unroll
        for (int j = 0; j < 8; j++) {
            __nv_bfloat16 b0 = __float2bfloat16(v[j]);
            float r1 = v[j] - __bfloat162float(b0);
            __nv_bfloat16 b1 = __float2bfloat16(r1);
            float r2 = r1 - __bfloat162float(b1);
            A0s[arow][akoff + j] = b0;
            A1s[arow][akoff + j] = b1;
            A2s[arow][akoff + j] = __float2bfloat16(r2);
        }
        __syncthreads();

        wmma::fragment<wmma::matrix_a, 16, 16, 16, __nv_bfloat16, wmma::row_major>
            a0[2], a1[2], a2[2];
#pragma unroll
        for (int mi = 0; mi < 2; mi++) {
            wmma::load_matrix_sync(a0[mi], &A0s[wm * 32 + mi * 16][0], 16);
            wmma::load_matrix_sync(a1[mi], &A1s[wm * 32 + mi * 16][0], 16);
            wmma::load_matrix_sync(a2[mi], &A2s[wm * 32 + mi * 16][0], 16);
        }
        wmma::fragment<wmma::matrix_b, 16, 16, 16, __nv_bfloat16, wmma::row_major>
            b0[2], b1[2], b2[2];
#pragma unroll
        for (int ni = 0; ni < 2; ni++) {
            size_t boff = (size_t)k0 * Ncol + n0 + wn * 32 + ni * 16;
            wmma::load_matrix_sync(b0[ni], W0 + boff, Ncol);
            wmma::load_matrix_sync(b1[ni], W1 + boff, Ncol);
            wmma::load_matrix_sync(b2[ni], W2 + boff, Ncol);
        }
#pragma unroll
        for (int mi = 0; mi < 2; mi++)
#pragma unroll
            for (int ni = 0; ni < 2; ni++) {
                wmma::mma_sync(acc0[mi][ni], a0[mi], b0[ni], acc0[mi][ni]);
                wmma::mma_sync(accR[mi][ni], a0[mi], b1[ni], accR[mi][ni]);
                wmma::mma_sync(accR[mi][ni], a1[mi], b0[ni], accR[mi][ni]);
                wmma::mma_sync(accR[mi][ni], a1[mi], b1[ni], accR[mi][ni]);
                wmma::mma_sync(accR[mi][ni], a0[mi], b2[ni], accR[mi][ni]);
                wmma::mma_sync(accR[mi][ni], a2[mi], b0[ni], accR[mi][ni]);
            }
    }

#pragma unroll
    for (int mi = 0; mi < 2; mi++)
#pragma unroll
        for (int ni = 0; ni < 2; ni++) {
#pragma unroll
            for (int e = 0; e < acc0[mi][ni].num_elements; e++)
                acc0[mi][ni].x[e] += accR[mi][ni].x[e];
            wmma::store_matrix_sync(&Cs[wm * 32 + mi * 16][wn * 32 + ni * 16],
                                    acc0[mi][ni], 64, wmma::mem_row_major);
        }
    __syncthreads();

    const int erow = tid >> 1;
    const int ecb = (tid & 1) << 5;
    float* crow = C + (size_t)(m0 + erow) * Ncol + n0 + ecb;
#pragma unroll
    for (int j = 0; j < 32; j += 4) {
        float4 vv = *(float4*)&Cs[erow][ecb + j];
        float y[4];
        const float* vp = (const float*)&vv;
#pragma unroll
        for (int q = 0; q < 4; q++) {
            int col = n0 + ecb + j + q;
            float yy;
            if (BN_RELU) {
                float s = __ldg(bng + col) * rsqrtf(__ldg(bnv + col) + 1e-5f);
                float off = (__ldg(bias + col) - __ldg(bnm + col)) * s + __ldg(bnb + col);
                yy = fmaxf(fmaf(vp[q], s, off), 0.0f);
            } else {
                yy = vp[q] + __ldg(bias + col);
            }
            y[q] = yy;
        }
        *(float4*)(crow + j) = make_float4(y[0], y[1], y[2], y[3]);
    }
}

// ---------------- zero pooled ---------------------------------------------------
__global__ void zero_pooled_kernel(float4* __restrict__ p) {
    int idx = blockIdx.x * blockDim.x + threadIdx.x;
    p[idx] = make_float4(0.f, 0.f, 0.f, 0.f);
}

// ---------------- graph pooling --------------------------------------------------
__global__ void pool_kernel(const float* __restrict__ t,
                            const int* __restrict__ batch,
                            float* __restrict__ pooled) {
    int idx = blockIdx.x * blockDim.x + threadIdx.x;
    int n = idx >> 6;
    int c = (idx & 63) << 2;
    int g = batch[n];
    float4 v = *(const float4*)(t + (size_t)n * H2 + c);
    float* p = pooled + (size_t)g * H2 + c;
    atomicAdd(p + 0, v.x);
    atomicAdd(p + 1, v.y);
    atomicAdd(p + 2, v.z);
    atomicAdd(p + 3, v.w);
}

// ---------------- final head ------------------------------------------------------
__global__ void final_kernel(const float* __restrict__ vn,
                             const float* __restrict__ pW1,
                             const float* __restrict__ pb1,
                             const float* __restrict__ pW2,
                             const float* __restrict__ pb2,
                             float* __restrict__ out) {
    int g = blockIdx.x;
    int j = threadIdx.x;
    __shared__ float vrow[H];
    vrow[j] = vn[(size_t)g * H + j];
    __syncthreads();
    float acc = pb1[j];
#pragma unroll 8
    for (int k = 0; k < H; k++) acc = fmaf(vrow[k], __ldg(pW1 + k * H + j), acc);
    float val = fmaxf(acc, 0.0f) * __ldg(pW2 + j);
#pragma unroll
    for (int o = 16; o > 0; o >>= 1) val += __shfl_down_sync(0xffffffffu, val, o);
    __shared__ float part[4];
    if ((j & 31) == 0) part[j >> 5] = val;
    __syncthreads();
    if (j == 0) {
        float s = part[0] + part[1] + part[2] + part[3] + pb2[0];
        out[g] = fminf(fmaxf(s, 0.0f), 50.0f);
    }
}

// ---------------- launch -----------------------------------------------------------
extern "C" void kernel_launch(void* const* d_in, const int* in_sizes, int n_in,
                              void* d_out, int out_size) {
    const int* x          = (const int*)d_in[0];
    const int* edge_index = (const int*)d_in[1];
    const int* edge_attr  = (const int*)d_in[2];
    const int* batch      = (const int*)d_in[3];
    const float* atom_emb  = (const float*)d_in[4];
    const float* vn_emb    = (const float*)d_in[5];
    const float* bond_emb  = (const float*)d_in[6];
    const float* conv_eps  = (const float*)d_in[7];
    const float* conv_W1   = (const float*)d_in[8];
    const float* conv_b1   = (const float*)d_in[9];
    const float* conv_bn_g = (const float*)d_in[10];
    const float* conv_bn_b = (const float*)d_in[11];
    const float* conv_bn_m = (const float*)d_in[12];
    const float* conv_bn_v = (const float*)d_in[13];
    const float* conv_W2   = (const float*)d_in[14];
    const float* conv_b2   = (const float*)d_in[15];
    const float* vn1_W  = (const float*)d_in[16];
    const float* vn1_b  = (const float*)d_in[17];
    const float* vn1_g  = (const float*)d_in[18];
    const float* vn1_be = (const float*)d_in[19];
    const float* vn1_m  = (const float*)d_in[20];
    const float* vn1_v  = (const float*)d_in[21];
    const float* vn2_W  = (const float*)d_in[22];
    const float* vn2_b  = (const float*)d_in[23];
    const float* vn2_g  = (const float*)d_in[24];
    const float* vn2_be = (const float*)d_in[25];
    const float* vn2_m  = (const float*)d_in[26];
    const float* vn2_v  = (const float*)d_in[27];
    const float* pW1 = (const float*)d_in[28];
    const float* pb1 = (const float*)d_in[29];
    const float* pW2 = (const float*)d_in[30];
    const float* pb2 = (const float*)d_in[31];
    float* out = (float*)d_out;

    float *h, *agg, *t, *vn, *pooled;
    __nv_bfloat16 *w0, *w1, *w2;
    cudaGetSymbolAddress((void**)&h, g_h);
    cudaGetSymbolAddress((void**)&agg, g_agg);
    cudaGetSymbolAddress((void**)&t, g_t);
    cudaGetSymbolAddress((void**)&vn, g_vn);
    cudaGetSymbolAddress((void**)&pooled, g_pooled);
    cudaGetSymbolAddress((void**)&w0, g_w0);
    cudaGetSymbolAddress((void**)&w1, g_w1);
    cudaGetSymbolAddress((void**)&w2, g_w2);

    // bf16x3 copies of W1, W2, V2 in original [K][N] layout
    const int OFF_W1 = 0;        // 128x256
    const int OFF_W2 = 32768;    // 256x128
    const int OFF_V2 = 65536;    // 256x128
    for (int i = 0; i < LAYERS; i++) {
        size_t off = (size_t)i * WT_L;
        wconv3_kernel<<<(H * H2 + 255) / 256, 256>>>(
            conv_W1 + (size_t)i * H * H2,
            w0 + off + OFF_W1, w1 + off + OFF_W1, w2 + off + OFF_W1, H * H2);
        wconv3_kernel<<<(H2 * H + 255) / 256, 256>>>(
            conv_W2 + (size_t)i * H2 * H,
            w0 + off + OFF_W2, w1 + off + OFF_W2, w2 + off + OFF_W2, H2 * H);
        wconv3_kernel<<<(H2 * H + 255) / 256, 256>>>(
            vn2_W + (size_t)i * H2 * H,
            w0 + off + OFF_V2, w1 + off + OFF_V2, w2 + off + OFF_V2, H2 * H);
    }

    atom_kernel<<<(N_NODES * 32) / 256, 256>>>(x, atom_emb, h);
    vninit_kernel<<<(N_GRAPHS * 32) / 256, 256>>>(vn_emb, vn);

    for (int i = 0; i < LAYERS; i++) {
        size_t off = (size_t)i * WT_L;
        addvn_kernel<<<(N_NODES * 32) / 256, 256>>>(h, vn, batch, agg);
        edge_kernel<<<N_EDGES / 8, 256>>>(edge_index, edge_attr,
                                          bond_emb + (size_t)i * FB * VB * H, h, agg);
        // conv1: t = relu(bn(((1+eps)h + agg) @ W1 + b1))  [N,256]  (bf16x3 WMMA)
        gemm_wmma3<1, true><<<dim3(N_NODES / 128, H2 / 64), 256>>>(
            h, agg,
            w0 + off + OFF_W1, w1 + off + OFF_W1, w2 + off + OFF_W1,
            conv_b1 + i * H2, conv_bn_g + i * H2, conv_bn_b + i * H2,
            conv_bn_m + i * H2, conv_bn_v + i * H2, t, N_NODES, H, H2,
            conv_eps + i);
        // conv2: h = t @ W2 + b2                            [N,128]  (bf16x3 WMMA)
        gemm_wmma3<0, false><<<dim3(N_NODES / 128, H / 64), 256>>>(
            t, nullptr,
            w0 + off + OFF_W2, w1 + off + OFF_W2, w2 + off + OFF_W2,
            conv_b2 + i * H, nullptr, nullptr, nullptr, nullptr,
            h, N_NODES, H2, H, nullptr);
        // vn1: t = relu(bn(concat(vn[batch], h) @ vn1_W + b))  [N,256]  (SIMT fp32)
        gemm_simt<2, true><<<dim3(N_NODES / 64, H2 / 64), 256>>>(
            h, vn, batch, vn1_W + (size_t)i * H2 * H2, vn1_b + i * H2,
            vn1_g + i * H2, vn1_be + i * H2, vn1_m + i * H2, vn1_v + i * H2,
            t, N_NODES, H2, H2, nullptr);
        zero_pooled_kernel<<<(N_GRAPHS * H2 / 4) / 256, 256>>>((float4*)pooled);
        pool_kernel<<<(N_NODES * 64) / 256, 256>>>(t, batch, pooled);
        // vn2: vn = relu(bn(pooled @ vn2_W + b))            [G,128]  (bf16x3 WMMA)
        gemm_wmma3<0, true><<<dim3(N_GRAPHS / 128, H / 64), 256>>>(
            pooled, nullptr,
            w0 + off + OFF_V2, w1 + off + OFF_V2, w2 + off + OFF_V2,
            vn2_b + i * H, vn2_g + i * H, vn2_be + i * H,
            vn2_m + i * H, vn2_v + i * H, vn, N_GRAPHS, H2, H, nullptr);
    }
    final_kernel<<<N_GRAPHS, 128>>>(vn, pW1, pb1, pW2, pb2, out);
}

// round 9
// speedup vs baseline: 1.0882x; 1.0882x over previous
#include <cuda_runtime.h>
#include <cuda_bf16.h>
#include <mma.h>

using namespace nvcuda;

#define N_NODES 262144
#define N_EDGES 1048576
#define N_GRAPHS 8192
#define H 128
#define H2 256
#define LAYERS 4
#define FA 9
#define VA 64
#define FB 3
#define VB 8

// ---------------- scratch ----------------------------------------------------
__device__ float g_h[(size_t)N_NODES * H];
__device__ float g_agg[(size_t)N_NODES * H];
__device__ float g_t[(size_t)N_NODES * H2];
__device__ float g_vn[(size_t)N_GRAPHS * H];
__device__ float g_pooled[(size_t)N_GRAPHS * H2];
// bf16 3-way split weights [K][N] for W1, W2, V1, V2
#define WT_L (32768 + 32768 + 65536 + 32768)   // 163840 per layer
__device__ __nv_bfloat16 g_w0[(size_t)LAYERS * WT_L];
__device__ __nv_bfloat16 g_w1[(size_t)LAYERS * WT_L];
__device__ __nv_bfloat16 g_w2[(size_t)LAYERS * WT_L];

// ---- elementwise bf16x3 weight split -----------------------------------------
__global__ void wconv3_kernel(const float* __restrict__ W,
                              __nv_bfloat16* __restrict__ W0,
                              __nv_bfloat16* __restrict__ W1,
                              __nv_bfloat16* __restrict__ W2, int total) {
    int idx = blockIdx.x * blockDim.x + threadIdx.x;
    if (idx >= total) return;
    float w = W[idx];
    __nv_bfloat16 b0 = __float2bfloat16(w);
    float r1 = w - __bfloat162float(b0);
    __nv_bfloat16 b1 = __float2bfloat16(r1);
    float r2 = r1 - __bfloat162float(b1);
    W0[idx] = b0;
    W1[idx] = b1;
    W2[idx] = __float2bfloat16(r2);
}

// ---------------- atom encoder ------------------------------------------------
__global__ void atom_kernel(const int* __restrict__ x,
                            const float* __restrict__ emb,
                            float* __restrict__ h) {
    int idx = blockIdx.x * blockDim.x + threadIdx.x;
    int n = idx >> 5;
    int c = (idx & 31) << 2;
    float4 acc = make_float4(0.f, 0.f, 0.f, 0.f);
#pragma unroll
    for (int f = 0; f < FA; f++) {
        int v = x[n * FA + f];
        float4 e = *(const float4*)(emb + ((size_t)(f * VA + v) * H) + c);
        acc.x += e.x; acc.y += e.y; acc.z += e.z; acc.w += e.w;
    }
    *(float4*)(h + (size_t)n * H + c) = acc;
}

// ---------------- vn init ------------------------------------------------------
__global__ void vninit_kernel(const float* __restrict__ vn_emb,
                              float* __restrict__ vn) {
    int idx = blockIdx.x * blockDim.x + threadIdx.x;
    int g = idx >> 5;
    int c = (idx & 31) << 2;
    *(float4*)(vn + (size_t)g * H + c) = *(const float4*)(vn_emb + c);
}

// ---------------- h += vn[batch]; agg = 0 --------------------------------------
__global__ void addvn_kernel(float* __restrict__ h,
                             const float* __restrict__ vn,
                             const int* __restrict__ batch,
                             float* __restrict__ agg) {
    int idx = blockIdx.x * blockDim.x + threadIdx.x;
    int n = idx >> 5;
    int c = (idx & 31) << 2;
    int g = batch[n];
    float4 hv = *(float4*)(h + (size_t)n * H + c);
    float4 vv = *(const float4*)(vn + (size_t)g * H + c);
    hv.x += vv.x; hv.y += vv.y; hv.z += vv.z; hv.w += vv.w;
    *(float4*)(h + (size_t)n * H + c) = hv;
    *(float4*)(agg + (size_t)n * H + c) = make_float4(0.f, 0.f, 0.f, 0.f);
}

// ---------------- edge message -------------------------------------------------
__global__ void edge_kernel(const int* __restrict__ ei,
                            const int* __restrict__ ea,
                            const float* __restrict__ bond,
                            const float* __restrict__ h,
                            float* __restrict__ agg) {
    __shared__ float tab[FB * VB * H];
    for (int i = threadIdx.x; i < FB * VB * H; i += blockDim.x) tab[i] = bond[i];
    __syncthreads();
    int e = (blockIdx.x * blockDim.x + threadIdx.x) >> 5;
    int lane = threadIdx.x & 31;
    int src = ei[e];
    int dst = ei[N_EDGES + e];
    int a0 = ea[e * 3 + 0], a1 = ea[e * 3 + 1], a2 = ea[e * 3 + 2];
    int c = lane << 2;
    float4 hv = *(const float4*)(h + (size_t)src * H + c);
    float4 e0 = *(const float4*)(tab + (0 * VB + a0) * H + c);
    float4 e1 = *(const float4*)(tab + (1 * VB + a1) * H + c);
    float4 e2 = *(const float4*)(tab + (2 * VB + a2) * H + c);
    float m0 = fmaxf(hv.x + e0.x + e1.x + e2.x, 0.f);
    float m1 = fmaxf(hv.y + e0.y + e1.y + e2.y, 0.f);
    float m2 = fmaxf(hv.z + e0.z + e1.z + e2.z, 0.f);
    float m3 = fmaxf(hv.w + e0.w + e1.w + e2.w, 0.f);
    float* p = agg + (size_t)dst * H + c;
    atomicAdd(p + 0, m0);
    atomicAdd(p + 1, m1);
    atomicAdd(p + 2, m2);
    atomicAdd(p + 3, m3);
}

// ======== bf16x3 WMMA GEMM v2: SMEM-staged B, padded layouts ===================
// Tile 128M x 64N, K-slab 32. 8 warps = 4m x 2n, warp tile 32x32.
// a = a0+a1+a2; acc0 = A0B0; accR = A0B1+A1B0+A1B1+A0B2+A2B0.
#define A_LD 40      // padded ldm for A slabs (elems)
#define B_LD 72      // padded ldm for B slabs (elems)
#define SM_A0 0
#define SM_A1 10240  // 128*40*2
#define SM_A2 20480
#define SM_B0 30720
#define SM_B1 35328  // +32*72*2
#define SM_B2 39936
#define SM_TOTAL 44544

template <int MODE_A, bool BN_RELU>
__global__ __launch_bounds__(256) void gemm_wmma3(
    const float* __restrict__ A, const float* __restrict__ A2,
    const int* __restrict__ batch,
    const __nv_bfloat16* __restrict__ W0, const __nv_bfloat16* __restrict__ W1,
    const __nv_bfloat16* __restrict__ W2,
    const float* __restrict__ bias,
    const float* __restrict__ bng, const float* __restrict__ bnb,
    const float* __restrict__ bnm, const float* __restrict__ bnv,
    float* __restrict__ C, int M, int K, int Ncol,
    const float* __restrict__ epsp) {
    __shared__ __align__(16) char smem[SM_TOTAL];
    __nv_bfloat16* A0s = (__nv_bfloat16*)(smem + SM_A0);
    __nv_bfloat16* A1s = (__nv_bfloat16*)(smem + SM_A1);
    __nv_bfloat16* A2s = (__nv_bfloat16*)(smem + SM_A2);
    __nv_bfloat16* B0s = (__nv_bfloat16*)(smem + SM_B0);
    __nv_bfloat16* B1s = (__nv_bfloat16*)(smem + SM_B1);
    __nv_bfloat16* B2s = (__nv_bfloat16*)(smem + SM_B2);
    float* Cs = (float*)smem;          // reused after mainloop (32 KB < 44.5 KB)

    const int tid = threadIdx.x;
    const int wid = tid >> 5;
    const int wm = wid & 3;            // warp row: 32 rows
    const int wn = wid >> 2;           // warp col: 32 cols
    const int m0 = blockIdx.x * 128;
    const int n0 = blockIdx.y * 64;

    // A loader: thread -> (row = tid>>1, 16-wide k chunk at (tid&1)*16)
    const int arow = tid >> 1;
    const int akoff = (tid & 1) << 4;
    const int grow = m0 + arow;
    // B loader: thread -> (row = tid>>3, 8-wide n chunk at (tid&7)*8)
    const int brow = tid >> 3;
    const int bcol = (tid & 7) << 3;

    float c0 = 1.0f;
    if (MODE_A == 1) c0 = 1.0f + __ldg(epsp);
    int bg = 0;
    if (MODE_A == 2) bg = batch[grow];

    wmma::fragment<wmma::accumulator, 16, 16, 16, float> acc0[2][2], accR[2][2];
#pragma unroll
    for (int mi = 0; mi < 2; mi++)
#pragma unroll
        for (int ni = 0; ni < 2; ni++) {
            wmma::fill_fragment(acc0[mi][ni], 0.0f);
            wmma::fill_fragment(accR[mi][ni], 0.0f);
        }

    for (int k0 = 0; k0 < K; k0 += 32) {
        // ---- stage A (combine + 3-way split), 16 elems per thread ----
        float v[16];
        {
            int gk = k0 + akoff;
            if (MODE_A == 0) {
#pragma unroll
                for (int q = 0; q < 4; q++)
                    *(float4*)&v[q * 4] = *(const float4*)(A + (size_t)grow * K + gk + q * 4);
            } else if (MODE_A == 1) {
#pragma unroll
                for (int q = 0; q < 4; q++) {
                    float4 hv = *(const float4*)(A + (size_t)grow * K + gk + q * 4);
                    float4 gv = *(const float4*)(A2 + (size_t)grow * K + gk + q * 4);
                    v[q*4+0] = fmaf(c0, hv.x, gv.x);
                    v[q*4+1] = fmaf(c0, hv.y, gv.y);
                    v[q*4+2] = fmaf(c0, hv.z, gv.z);
                    v[q*4+3] = fmaf(c0, hv.w, gv.w);
                }
            } else {
                const float* base = (gk < H) ? (A2 + (size_t)bg * H + gk)
                                             : (A + (size_t)grow * H + (gk - H));
#pragma unroll
                for (int q = 0; q < 4; q++)
                    *(float4*)&v[q * 4] = *(const float4*)(base + q * 4);
            }
        }
        __syncthreads();   // previous slab fully consumed (and Cs not yet used)
#pragma unroll
        for (int j = 0; j < 16; j++) {
            __nv_bfloat16 b0 = __float2bfloat16(v[j]);
            float r1 = v[j] - __bfloat162float(b0);
            __nv_bfloat16 b1 = __float2bfloat16(r1);
            float r2 = r1 - __bfloat162float(b1);
            A0s[arow * A_LD + akoff + j] = b0;
            A1s[arow * A_LD + akoff + j] = b1;
            A2s[arow * A_LD + akoff + j] = __float2bfloat16(r2);
        }
        // ---- stage B (coalesced uint4 from global, 8 bf16 per split) ----
        {
            size_t goff = (size_t)(k0 + brow) * Ncol + n0 + bcol;
            int soff = brow * B_LD + bcol;
            *(uint4*)&B0s[soff] = *(const uint4*)(W0 + goff);
            *(uint4*)&B1s[soff] = *(const uint4*)(W1 + goff);
            *(uint4*)&B2s[soff] = *(const uint4*)(W2 + goff);
        }
        __syncthreads();

        // ---- MMA over the 32-deep slab (2 chunks of 16) ----
#pragma unroll
        for (int kk = 0; kk < 2; kk++) {
            wmma::fragment<wmma::matrix_a, 16, 16, 16, __nv_bfloat16, wmma::row_major>
                a0[2], a1[2], a2[2];
#pragma unroll
            for (int mi = 0; mi < 2; mi++) {
                int ao = (wm * 32 + mi * 16) * A_LD + kk * 16;
                wmma::load_matrix_sync(a0[mi], A0s + ao, A_LD);
                wmma::load_matrix_sync(a1[mi], A1s + ao, A_LD);
                wmma::load_matrix_sync(a2[mi], A2s + ao, A_LD);
            }
#pragma unroll
            for (int ni = 0; ni < 2; ni++) {
                wmma::fragment<wmma::matrix_b, 16, 16, 16, __nv_bfloat16, wmma::row_major>
                    b0, b1, b2;
                int bo = (kk * 16) * B_LD + wn * 32 + ni * 16;
                wmma::load_matrix_sync(b0, B0s + bo, B_LD);
                wmma::load_matrix_sync(b1, B1s + bo, B_LD);
                wmma::load_matrix_sync(b2, B2s + bo, B_LD);
#pragma unroll
                for (int mi = 0; mi < 2; mi++) {
                    wmma::mma_sync(acc0[mi][ni], a0[mi], b0, acc0[mi][ni]);
                    wmma::mma_sync(accR[mi][ni], a0[mi], b1, accR[mi][ni]);
                    wmma::mma_sync(accR[mi][ni], a1[mi], b0, accR[mi][ni]);
                    wmma::mma_sync(accR[mi][ni], a1[mi], b1, accR[mi][ni]);
                    wmma::mma_sync(accR[mi][ni], a0[mi], b2, accR[mi][ni]);
                    wmma::mma_sync(accR[mi][ni], a2[mi], b0, accR[mi][ni]);
                }
            }
        }
    }

    __syncthreads();   // all MMA reads of A/B SMEM done before Cs overwrite
#pragma unroll
    for (int mi = 0; mi < 2; mi++)
#pragma unroll
        for (int ni = 0; ni < 2; ni++) {
#pragma unroll
            for (int e = 0; e < acc0[mi][ni].num_elements; e++)
                acc0[mi][ni].x[e] += accR[mi][ni].x[e];
            wmma::store_matrix_sync(&Cs[(wm * 32 + mi * 16) * 64 + wn * 32 + ni * 16],
                                    acc0[mi][ni], 64, wmma::mem_row_major);
        }
    __syncthreads();

    // epilogue: BN(+bias)+ReLU or bias
    const int erow = tid >> 1;
    const int ecb = (tid & 1) << 5;
    float* crow = C + (size_t)(m0 + erow) * Ncol + n0 + ecb;
#pragma unroll
    for (int j = 0; j < 32; j += 4) {
        float4 vv = *(float4*)&Cs[erow * 64 + ecb + j];
        float y[4];
        const float* vp = (const float*)&vv;
#pragma unroll
        for (int q = 0; q < 4; q++) {
            int col = n0 + ecb + j + q;
            float yy;
            if (BN_RELU) {
                float s = __ldg(bng + col) * rsqrtf(__ldg(bnv + col) + 1e-5f);
                float off = (__ldg(bias + col) - __ldg(bnm + col)) * s + __ldg(bnb + col);
                yy = fmaxf(fmaf(vp[q], s, off), 0.0f);
            } else {
                yy = vp[q] + __ldg(bias + col);
            }
            y[q] = yy;
        }
        *(float4*)(crow + j) = make_float4(y[0], y[1], y[2], y[3]);
    }
}

// ---------------- zero pooled ---------------------------------------------------
__global__ void zero_pooled_kernel(float4* __restrict__ p) {
    int idx = blockIdx.x * blockDim.x + threadIdx.x;
    p[idx] = make_float4(0.f, 0.f, 0.f, 0.f);
}

// ---------------- graph pooling --------------------------------------------------
__global__ void pool_kernel(const float* __restrict__ t,
                            const int* __restrict__ batch,
                            float* __restrict__ pooled) {
    int idx = blockIdx.x * blockDim.x + threadIdx.x;
    int n = idx >> 6;
    int c = (idx & 63) << 2;
    int g = batch[n];
    float4 v = *(const float4*)(t + (size_t)n * H2 + c);
    float* p = pooled + (size_t)g * H2 + c;
    atomicAdd(p + 0, v.x);
    atomicAdd(p + 1, v.y);
    atomicAdd(p + 2, v.z);
    atomicAdd(p + 3, v.w);
}

// ---------------- final head ------------------------------------------------------
__global__ void final_kernel(const float* __restrict__ vn,
                             const float* __restrict__ pW1,
                             const float* __restrict__ pb1,
                             const float* __restrict__ pW2,
                             const float* __restrict__ pb2,
                             float* __restrict__ out) {
    int g = blockIdx.x;
    int j = threadIdx.x;
    __shared__ float vrow[H];
    vrow[j] = vn[(size_t)g * H + j];
    __syncthreads();
    float acc = pb1[j];
#pragma unroll 8
    for (int k = 0; k < H; k++) acc = fmaf(vrow[k], __ldg(pW1 + k * H + j), acc);
    float val = fmaxf(acc, 0.0f) * __ldg(pW2 + j);
#pragma unroll
    for (int o = 16; o > 0; o >>= 1) val += __shfl_down_sync(0xffffffffu, val, o);
    __shared__ float part[4];
    if ((j & 31) == 0) part[j >> 5] = val;
    __syncthreads();
    if (j == 0) {
        float s = part[0] + part[1] + part[2] + part[3] + pb2[0];
        out[g] = fminf(fmaxf(s, 0.0f), 50.0f);
    }
}

// ---------------- launch -----------------------------------------------------------
extern "C" void kernel_launch(void* const* d_in, const int* in_sizes, int n_in,
                              void* d_out, int out_size) {
    const int* x          = (const int*)d_in[0];
    const int* edge_index = (const int*)d_in[1];
    const int* edge_attr  = (const int*)d_in[2];
    const int* batch      = (const int*)d_in[3];
    const float* atom_emb  = (const float*)d_in[4];
    const float* vn_emb    = (const float*)d_in[5];
    const float* bond_emb  = (const float*)d_in[6];
    const float* conv_eps  = (const float*)d_in[7];
    const float* conv_W1   = (const float*)d_in[8];
    const float* conv_b1   = (const float*)d_in[9];
    const float* conv_bn_g = (const float*)d_in[10];
    const float* conv_bn_b = (const float*)d_in[11];
    const float* conv_bn_m = (const float*)d_in[12];
    const float* conv_bn_v = (const float*)d_in[13];
    const float* conv_W2   = (const float*)d_in[14];
    const float* conv_b2   = (const float*)d_in[15];
    const float* vn1_W  = (const float*)d_in[16];
    const float* vn1_b  = (const float*)d_in[17];
    const float* vn1_g  = (const float*)d_in[18];
    const float* vn1_be = (const float*)d_in[19];
    const float* vn1_m  = (const float*)d_in[20];
    const float* vn1_v  = (const float*)d_in[21];
    const float* vn2_W  = (const float*)d_in[22];
    const float* vn2_b  = (const float*)d_in[23];
    const float* vn2_g  = (const float*)d_in[24];
    const float* vn2_be = (const float*)d_in[25];
    const float* vn2_m  = (const float*)d_in[26];
    const float* vn2_v  = (const float*)d_in[27];
    const float* pW1 = (const float*)d_in[28];
    const float* pb1 = (const float*)d_in[29];
    const float* pW2 = (const float*)d_in[30];
    const float* pb2 = (const float*)d_in[31];
    float* out = (float*)d_out;

    float *h, *agg, *t, *vn, *pooled;
    __nv_bfloat16 *w0, *w1, *w2;
    cudaGetSymbolAddress((void**)&h, g_h);
    cudaGetSymbolAddress((void**)&agg, g_agg);
    cudaGetSymbolAddress((void**)&t, g_t);
    cudaGetSymbolAddress((void**)&vn, g_vn);
    cudaGetSymbolAddress((void**)&pooled, g_pooled);
    cudaGetSymbolAddress((void**)&w0, g_w0);
    cudaGetSymbolAddress((void**)&w1, g_w1);
    cudaGetSymbolAddress((void**)&w2, g_w2);

    // bf16x3 copies of W1, W2, V1, V2 in original [K][N] layout
    const int OFF_W1 = 0;         // 128x256
    const int OFF_W2 = 32768;     // 256x128
    const int OFF_V1 = 65536;     // 256x256
    const int OFF_V2 = 131072;    // 256x128
    for (int i = 0; i < LAYERS; i++) {
        size_t off = (size_t)i * WT_L;
        wconv3_kernel<<<(H * H2 + 255) / 256, 256>>>(
            conv_W1 + (size_t)i * H * H2,
            w0 + off + OFF_W1, w1 + off + OFF_W1, w2 + off + OFF_W1, H * H2);
        wconv3_kernel<<<(H2 * H + 255) / 256, 256>>>(
            conv_W2 + (size_t)i * H2 * H,
            w0 + off + OFF_W2, w1 + off + OFF_W2, w2 + off + OFF_W2, H2 * H);
        wconv3_kernel<<<(H2 * H2 + 255) / 256, 256>>>(
            vn1_W + (size_t)i * H2 * H2,
            w0 + off + OFF_V1, w1 + off + OFF_V1, w2 + off + OFF_V1, H2 * H2);
        wconv3_kernel<<<(H2 * H + 255) / 256, 256>>>(
            vn2_W + (size_t)i * H2 * H,
            w0 + off + OFF_V2, w1 + off + OFF_V2, w2 + off + OFF_V2, H2 * H);
    }

    atom_kernel<<<(N_NODES * 32) / 256, 256>>>(x, atom_emb, h);
    vninit_kernel<<<(N_GRAPHS * 32) / 256, 256>>>(vn_emb, vn);

    for (int i = 0; i < LAYERS; i++) {
        size_t off = (size_t)i * WT_L;
        addvn_kernel<<<(N_NODES * 32) / 256, 256>>>(h, vn, batch, agg);
        edge_kernel<<<N_EDGES / 8, 256>>>(edge_index, edge_attr,
                                          bond_emb + (size_t)i * FB * VB * H, h, agg);
        // conv1: t = relu(bn(((1+eps)h + agg) @ W1 + b1))  [N,256]
        gemm_wmma3<1, true><<<dim3(N_NODES / 128, H2 / 64), 256>>>(
            h, agg, nullptr,
            w0 + off + OFF_W1, w1 + off + OFF_W1, w2 + off + OFF_W1,
            conv_b1 + i * H2, conv_bn_g + i * H2, conv_bn_b + i * H2,
            conv_bn_m + i * H2, conv_bn_v + i * H2, t, N_NODES, H, H2,
            conv_eps + i);
        // conv2: h = t @ W2 + b2                            [N,128]
        gemm_wmma3<0, false><<<dim3(N_NODES / 128, H / 64), 256>>>(
            t, nullptr, nullptr,
            w0 + off + OFF_W2, w1 + off + OFF_W2, w2 + off + OFF_W2,
            conv_b2 + i * H, nullptr, nullptr, nullptr, nullptr,
            h, N_NODES, H2, H, nullptr);
        // vn1: t = relu(bn(concat(vn[batch], h) @ vn1_W + b))  [N,256]
        gemm_wmma3<2, true><<<dim3(N_NODES / 128, H2 / 64), 256>>>(
            h, vn, batch,
            w0 + off + OFF_V1, w1 + off + OFF_V1, w2 + off + OFF_V1,
            vn1_b + i * H2, vn1_g + i * H2, vn1_be + i * H2,
            vn1_m + i * H2, vn1_v + i * H2, t, N_NODES, H2, H2, nullptr);
        zero_pooled_kernel<<<(N_GRAPHS * H2 / 4) / 256, 256>>>((float4*)pooled);
        pool_kernel<<<(N_NODES * 64) / 256, 256>>>(t, batch, pooled);
        // vn2: vn = relu(bn(pooled @ vn2_W + b))            [G,128]
        gemm_wmma3<0, true><<<dim3(N_GRAPHS / 128, H / 64), 256>>>(
            pooled, nullptr, nullptr,
            w0 + off + OFF_V2, w1 + off + OFF_V2, w2 + off + OFF_V2,
            vn2_b + i * H, vn2_g + i * H, vn2_be + i * H,
            vn2_m + i * H, vn2_v + i * H, vn, N_GRAPHS, H2, H, nullptr);
    }
    final_kernel<<<N_GRAPHS, 128>>>(vn, pW1, pb1, pW2, pb2, out);
}

// round 11
// speedup vs baseline: 1.2291x; 1.1295x over previous
#include <cuda_runtime.h>
#include <cuda_bf16.h>
#include <mma.h>

using namespace nvcuda;

#define N_NODES 262144
#define N_EDGES 1048576
#define N_GRAPHS 8192
#define H 128
#define H2 256
#define LAYERS 4
#define FA 9
#define VA 64
#define FB 3
#define VB 8

// ---------------- scratch ----------------------------------------------------
__device__ float g_h[(size_t)N_NODES * H];
__device__ float g_agg[(size_t)N_NODES * H];
__device__ float g_t[(size_t)N_NODES * H2];
__device__ float g_vn[(size_t)N_GRAPHS * H];
__device__ float g_pooled[(size_t)N_GRAPHS * H2];
// bf16x3 weights [K][N]
#define WT_L (32768 + 32768 + 65536 + 32768)   // 163840 per layer
__device__ __nv_bfloat16 g_w0[(size_t)LAYERS * WT_L];
__device__ __nv_bfloat16 g_w1[(size_t)LAYERS * WT_L];
__device__ __nv_bfloat16 g_w2[(size_t)LAYERS * WT_L];
// bf16x3 activation scratch
__device__ __nv_bfloat16 g_Z0[(size_t)N_NODES * H],  g_Z1[(size_t)N_NODES * H],  g_Z2[(size_t)N_NODES * H];
__device__ __nv_bfloat16 g_T0[(size_t)N_NODES * H2], g_T1[(size_t)N_NODES * H2], g_T2[(size_t)N_NODES * H2];
__device__ __nv_bfloat16 g_H0[(size_t)N_NODES * H],  g_H1[(size_t)N_NODES * H],  g_H2[(size_t)N_NODES * H];
__device__ __nv_bfloat16 g_V0[(size_t)N_GRAPHS * H], g_V1[(size_t)N_GRAPHS * H], g_V2[(size_t)N_GRAPHS * H];
__device__ __nv_bfloat16 g_P0[(size_t)N_GRAPHS * H2],g_P1[(size_t)N_GRAPHS * H2],g_P2[(size_t)N_GRAPHS * H2];

__device__ __forceinline__ void split3(float v, __nv_bfloat16& o0,
                                       __nv_bfloat16& o1, __nv_bfloat16& o2) {
    o0 = __float2bfloat16(v);
    float r1 = v - __bfloat162float(o0);
    o1 = __float2bfloat16(r1);
    o2 = __float2bfloat16(r1 - __bfloat162float(o1));
}

__device__ __forceinline__ void cp16(void* dst, const void* src) {
    unsigned d = (unsigned)__cvta_generic_to_shared(dst);
    asm volatile("cp.async.cg.shared.global [%0], [%1], 16;\n" :: "r"(d), "l"(src));
}

// ---- bf16x3 weight split ------------------------------------------------------
__global__ void wconv3_kernel(const float* __restrict__ W,
                              __nv_bfloat16* __restrict__ W0,
                              __nv_bfloat16* __restrict__ W1,
                              __nv_bfloat16* __restrict__ W2, int total) {
    int idx = blockIdx.x * blockDim.x + threadIdx.x;
    if (idx >= total) return;
    split3(W[idx], W0[idx], W1[idx], W2[idx]);
}

// ---- elementwise split of an f32 array -----------------------------------------
__global__ void split_plain_kernel(const float* __restrict__ src,
                                   __nv_bfloat16* __restrict__ D0,
                                   __nv_bfloat16* __restrict__ D1,
                                   __nv_bfloat16* __restrict__ D2) {
    int idx = blockIdx.x * blockDim.x + threadIdx.x;   // total/4 threads
    float4 v = *(const float4*)(src + (size_t)idx * 4);
    __nv_bfloat16 a0[4], a1[4], a2[4];
    split3(v.x, a0[0], a1[0], a2[0]);
    split3(v.y, a0[1], a1[1], a2[1]);
    split3(v.z, a0[2], a1[2], a2[2]);
    split3(v.w, a0[3], a1[3], a2[3]);
    *(uint2*)(D0 + (size_t)idx * 4) = *(uint2*)a0;
    *(uint2*)(D1 + (size_t)idx * 4) = *(uint2*)a1;
    *(uint2*)(D2 + (size_t)idx * 4) = *(uint2*)a2;
}

// ---- z = (1+eps)h + agg, split to bf16x3 ---------------------------------------
__global__ void split_z_kernel(const float* __restrict__ h,
                               const float* __restrict__ agg,
                               const float* __restrict__ epsp,
                               __nv_bfloat16* __restrict__ Z0,
                               __nv_bfloat16* __restrict__ Z1,
                               __nv_bfloat16* __restrict__ Z2) {
    int idx = blockIdx.x * blockDim.x + threadIdx.x;   // N*H/4 threads
    float c0 = 1.0f + __ldg(epsp);
    float4 hv = *(const float4*)(h + (size_t)idx * 4);
    float4 gv = *(const float4*)(agg + (size_t)idx * 4);
    float z[4] = { fmaf(c0, hv.x, gv.x), fmaf(c0, hv.y, gv.y),
                   fmaf(c0, hv.z, gv.z), fmaf(c0, hv.w, gv.w) };
    __nv_bfloat16 a0[4], a1[4], a2[4];
#pragma unroll
    for (int q = 0; q < 4; q++) split3(z[q], a0[q], a1[q], a2[q]);
    *(uint2*)(Z0 + (size_t)idx * 4) = *(uint2*)a0;
    *(uint2*)(Z1 + (size_t)idx * 4) = *(uint2*)a1;
    *(uint2*)(Z2 + (size_t)idx * 4) = *(uint2*)a2;
}

// ---------------- atom encoder ---------------------------------------------------
__global__ void atom_kernel(const int* __restrict__ x,
                            const float* __restrict__ emb,
                            float* __restrict__ h) {
    int idx = blockIdx.x * blockDim.x + threadIdx.x;
    int n = idx >> 5;
    int c = (idx & 31) << 2;
    float4 acc = make_float4(0.f, 0.f, 0.f, 0.f);
#pragma unroll
    for (int f = 0; f < FA; f++) {
        int v = x[n * FA + f];
        float4 e = *(const float4*)(emb + ((size_t)(f * VA + v) * H) + c);
        acc.x += e.x; acc.y += e.y; acc.z += e.z; acc.w += e.w;
    }
    *(float4*)(h + (size_t)n * H + c) = acc;
}

__global__ void vninit_kernel(const float* __restrict__ vn_emb,
                              float* __restrict__ vn) {
    int idx = blockIdx.x * blockDim.x + threadIdx.x;
    int g = idx >> 5;
    int c = (idx & 31) << 2;
    *(float4*)(vn + (size_t)g * H + c) = *(const float4*)(vn_emb + c);
}

__global__ void addvn_kernel(float* __restrict__ h,
                             const float* __restrict__ vn,
                             const int* __restrict__ batch,
                             float* __restrict__ agg) {
    int idx = blockIdx.x * blockDim.x + threadIdx.x;
    int n = idx >> 5;
    int c = (idx & 31) << 2;
    int g = batch[n];
    float4 hv = *(float4*)(h + (size_t)n * H + c);
    float4 vv = *(const float4*)(vn + (size_t)g * H + c);
    hv.x += vv.x; hv.y += vv.y; hv.z += vv.z; hv.w += vv.w;
    *(float4*)(h + (size_t)n * H + c) = hv;
    *(float4*)(agg + (size_t)n * H + c) = make_float4(0.f, 0.f, 0.f, 0.f);
}

__global__ void edge_kernel(const int* __restrict__ ei,
                            const int* __restrict__ ea,
                            const float* __restrict__ bond,
                            const float* __restrict__ h,
                            float* __restrict__ agg) {
    __shared__ float tab[FB * VB * H];
    for (int i = threadIdx.x; i < FB * VB * H; i += blockDim.x) tab[i] = bond[i];
    __syncthreads();
    int e = (blockIdx.x * blockDim.x + threadIdx.x) >> 5;
    int lane = threadIdx.x & 31;
    int src = ei[e];
    int dst = ei[N_EDGES + e];
    int a0 = ea[e * 3 + 0], a1 = ea[e * 3 + 1], a2 = ea[e * 3 + 2];
    int c = lane << 2;
    float4 hv = *(const float4*)(h + (size_t)src * H + c);
    float4 e0 = *(const float4*)(tab + (0 * VB + a0) * H + c);
    float4 e1 = *(const float4*)(tab + (1 * VB + a1) * H + c);
    float4 e2 = *(const float4*)(tab + (2 * VB + a2) * H + c);
    float m0 = fmaxf(hv.x + e0.x + e1.x + e2.x, 0.f);
    float m1 = fmaxf(hv.y + e0.y + e1.y + e2.y, 0.f);
    float m2 = fmaxf(hv.z + e0.z + e1.z + e2.z, 0.f);
    float m3 = fmaxf(hv.w + e0.w + e1.w + e2.w, 0.f);
    float* p = agg + (size_t)dst * H + c;
    atomicAdd(p + 0, m0);
    atomicAdd(p + 1, m1);
    atomicAdd(p + 2, m2);
    atomicAdd(p + 3, m3);
}

// ======== bf16x3 GEMM v3: pre-split A, cp.async double-buffered =================
// Tile 128M x 64N, K-slab 16. 8 warps = 4m x 2n, warp tile 32x32.
// MODE_A: 0 = A from (A0g,A1g,A2g)[M,K]; 2 = concat(V[batch][G,128], A[M,128]).
#define BK 16
#define A_LD 16
#define B_LD 72
#define OFF_A0 0
#define OFF_A1 4096
#define OFF_A2 8192
#define OFF_B0 12288
#define OFF_B1 14592
#define OFF_B2 16896
#define STAGE  19200   // bytes per stage; x2 = 38400

template <int MODE_A, bool BN_RELU, bool OUT_F32, bool OUT_SPLIT>
__global__ __launch_bounds__(256, 2) void gemm3(
    const __nv_bfloat16* __restrict__ A0g, const __nv_bfloat16* __restrict__ A1g,
    const __nv_bfloat16* __restrict__ A2g,
    const __nv_bfloat16* __restrict__ V0g, const __nv_bfloat16* __restrict__ V1g,
    const __nv_bfloat16* __restrict__ V2g,
    const int* __restrict__ batch,
    const __nv_bfloat16* __restrict__ W0, const __nv_bfloat16* __restrict__ W1,
    const __nv_bfloat16* __restrict__ W2,
    const float* __restrict__ bias,
    const float* __restrict__ bng, const float* __restrict__ bnb,
    const float* __restrict__ bnm, const float* __restrict__ bnv,
    float* __restrict__ Cf,
    __nv_bfloat16* __restrict__ C0, __nv_bfloat16* __restrict__ C1,
    __nv_bfloat16* __restrict__ C2,
    int M, int K, int Ncol) {
    __shared__ __align__(16) char smem[2 * STAGE];

    const int tid = threadIdx.x;
    const int wid = tid >> 5;
    const int wm = wid & 3;
    const int wn = wid >> 2;
    const int m0 = blockIdx.x * 128;
    const int n0 = blockIdx.y * 64;

    const int arow = tid >> 1;
    const int ac8 = (tid & 1) << 3;          // 0 or 8 elems (16B chunk)
    const int grow = m0 + arow;
    int bg = 0;
    if (MODE_A == 2) bg = batch[grow];

    wmma::fragment<wmma::accumulator, 16, 16, 16, float> acc0[2][2], accR[2][2];
#pragma unroll
    for (int mi = 0; mi < 2; mi++)
#pragma unroll
        for (int ni = 0; ni < 2; ni++) {
            wmma::fill_fragment(acc0[mi][ni], 0.0f);
            wmma::fill_fragment(accR[mi][ni], 0.0f);
        }

    auto stage = [&](int kt, int buf) {
        char* base = smem + buf * STAGE;
        int gk = kt * BK + ac8;
        const __nv_bfloat16 *s0, *s1, *s2;
        if (MODE_A == 0) {
            size_t o = (size_t)grow * K + gk;
            s0 = A0g + o; s1 = A1g + o; s2 = A2g + o;
        } else {
            if (gk < H) {
                size_t o = (size_t)bg * H + gk;
                s0 = V0g + o; s1 = V1g + o; s2 = V2g + o;
            } else {
                size_t o = (size_t)grow * H + (gk - H);
                s0 = A0g + o; s1 = A1g + o; s2 = A2g + o;
            }
        }
        int soff = (arow * A_LD + ac8) * 2;
        cp16(base + OFF_A0 + soff, s0);
        cp16(base + OFF_A1 + soff, s1);
        cp16(base + OFF_A2 + soff, s2);
        // B: 3 splits x 16 rows x 64 cols = 384 16B-chunks
#pragma unroll
        for (int c = tid; c < 384; c += 256) {
            int sp = c >> 7, r = (c & 127) >> 3, ch = c & 7;
            size_t go = (size_t)(kt * BK + r) * Ncol + n0 + ch * 8;
            const __nv_bfloat16* src = (sp == 0) ? (W0 + go) : (sp == 1) ? (W1 + go) : (W2 + go);
            cp16(base + OFF_B0 + sp * 2304 + (r * B_LD + ch * 8) * 2, src);
        }
        asm volatile("cp.async.commit_group;\n" ::);
    };

    const int KT = K / BK;
    stage(0, 0);
    for (int kt = 0; kt < KT; kt++) {
        if (kt + 1 < KT) {
            stage(kt + 1, (kt + 1) & 1);
            asm volatile("cp.async.wait_group 1;\n" ::);
        } else {
            asm volatile("cp.async.wait_group 0;\n" ::);
        }
        __syncthreads();
        char* base = smem + (kt & 1) * STAGE;
        const __nv_bfloat16* Ab0 = (const __nv_bfloat16*)(base + OFF_A0);
        const __nv_bfloat16* Ab1 = (const __nv_bfloat16*)(base + OFF_A1);
        const __nv_bfloat16* Ab2 = (const __nv_bfloat16*)(base + OFF_A2);
        const __nv_bfloat16* Bb0 = (const __nv_bfloat16*)(base + OFF_B0);
        const __nv_bfloat16* Bb1 = (const __nv_bfloat16*)(base + OFF_B1);
        const __nv_bfloat16* Bb2 = (const __nv_bfloat16*)(base + OFF_B2);

        wmma::fragment<wmma::matrix_a, 16, 16, 16, __nv_bfloat16, wmma::row_major>
            a0[2], a1[2], a2[2];
#pragma unroll
        for (int mi = 0; mi < 2; mi++) {
            int ao = (wm * 32 + mi * 16) * A_LD;
            wmma::load_matrix_sync(a0[mi], Ab0 + ao, A_LD);
            wmma::load_matrix_sync(a1[mi], Ab1 + ao, A_LD);
            wmma::load_matrix_sync(a2[mi], Ab2 + ao, A_LD);
        }
#pragma unroll
        for (int ni = 0; ni < 2; ni++) {
            wmma::fragment<wmma::matrix_b, 16, 16, 16, __nv_bfloat16, wmma::row_major> b0, b1, b2;
            int bo = wn * 32 + ni * 16;
            wmma::load_matrix_sync(b0, Bb0 + bo, B_LD);
            wmma::load_matrix_sync(b1, Bb1 + bo, B_LD);
            wmma::load_matrix_sync(b2, Bb2 + bo, B_LD);
#pragma unroll
            for (int mi = 0; mi < 2; mi++) {
                wmma::mma_sync(acc0[mi][ni], a0[mi], b0, acc0[mi][ni]);
                wmma::mma_sync(accR[mi][ni], a0[mi], b1, accR[mi][ni]);
                wmma::mma_sync(accR[mi][ni], a1[mi], b0, accR[mi][ni]);
                wmma::mma_sync(accR[mi][ni], a1[mi], b1, accR[mi][ni]);
                wmma::mma_sync(accR[mi][ni], a0[mi], b2, accR[mi][ni]);
                wmma::mma_sync(accR[mi][ni], a2[mi], b0, accR[mi][ni]);
            }
        }
        __syncthreads();
    }

    // park combined result in SMEM (aliases stage buffers; all reads done)
    float* Cs = (float*)smem;
#pragma unroll
    for (int mi = 0; mi < 2; mi++)
#pragma unroll
        for (int ni = 0; ni < 2; ni++) {
#pragma unroll
            for (int e = 0; e < acc0[mi][ni].num_elements; e++)
                acc0[mi][ni].x[e] += accR[mi][ni].x[e];
            wmma::store_matrix_sync(&Cs[(wm * 32 + mi * 16) * 64 + wn * 32 + ni * 16],
                                    acc0[mi][ni], 64, wmma::mem_row_major);
        }
    __syncthreads();

    const int erow = tid >> 1;
    const int ecb = (tid & 1) << 5;
    const size_t rowoff = (size_t)(m0 + erow) * Ncol;
#pragma unroll
    for (int j = 0; j < 32; j += 4) {
        float y[4];
#pragma unroll
        for (int q = 0; q < 4; q++) {
            int col = n0 + ecb + j + q;
            float v = Cs[erow * 64 + ecb + j + q];
            if (BN_RELU) {
                float s = __ldg(bng + col) * rsqrtf(__ldg(bnv + col) + 1e-5f);
                float off = (__ldg(bias + col) - __ldg(bnm + col)) * s + __ldg(bnb + col);
                y[q] = fmaxf(fmaf(v, s, off), 0.0f);
            } else {
                y[q] = v + __ldg(bias + col);
            }
        }
        size_t o = rowoff + n0 + ecb + j;
        if (OUT_F32)
            *(float4*)(Cf + o) = make_float4(y[0], y[1], y[2], y[3]);
        if (OUT_SPLIT) {
            __nv_bfloat16 s0[4], s1[4], s2[4];
#pragma unroll
            for (int q = 0; q < 4; q++) split3(y[q], s0[q], s1[q], s2[q]);
            *(uint2*)(C0 + o) = *(uint2*)s0;
            *(uint2*)(C1 + o) = *(uint2*)s1;
            *(uint2*)(C2 + o) = *(uint2*)s2;
        }
    }
}

// ---------------- zero pooled -----------------------------------------------------
__global__ void zero_pooled_kernel(float4* __restrict__ p) {
    int idx = blockIdx.x * blockDim.x + threadIdx.x;
    p[idx] = make_float4(0.f, 0.f, 0.f, 0.f);
}

__global__ void pool_kernel(const float* __restrict__ t,
                            const int* __restrict__ batch,
                            float* __restrict__ pooled) {
    int idx = blockIdx.x * blockDim.x + threadIdx.x;
    int n = idx >> 6;
    int c = (idx & 63) << 2;
    int g = batch[n];
    float4 v = *(const float4*)(t + (size_t)n * H2 + c);
    float* p = pooled + (size_t)g * H2 + c;
    atomicAdd(p + 0, v.x);
    atomicAdd(p + 1, v.y);
    atomicAdd(p + 2, v.z);
    atomicAdd(p + 3, v.w);
}

__global__ void final_kernel(const float* __restrict__ vn,
                             const float* __restrict__ pW1,
                             const float* __restrict__ pb1,
                             const float* __restrict__ pW2,
                             const float* __restrict__ pb2,
                             float* __restrict__ out) {
    int g = blockIdx.x;
    int j = threadIdx.x;
    __shared__ float vrow[H];
    vrow[j] = vn[(size_t)g * H + j];
    __syncthreads();
    float acc = pb1[j];
#pragma unroll 8
    for (int k = 0; k < H; k++) acc = fmaf(vrow[k], __ldg(pW1 + k * H + j), acc);
    float val = fmaxf(acc, 0.0f) * __ldg(pW2 + j);
#pragma unroll
    for (int o = 16; o > 0; o >>= 1) val += __shfl_down_sync(0xffffffffu, val, o);
    __shared__ float part[4];
    if ((j & 31) == 0) part[j >> 5] = val;
    __syncthreads();
    if (j == 0) {
        float s = part[0] + part[1] + part[2] + part[3] + pb2[0];
        out[g] = fminf(fmaxf(s, 0.0f), 50.0f);
    }
}

// ---------------- launch -------------------------------------------------------------
extern "C" void kernel_launch(void* const* d_in, const int* in_sizes, int n_in,
                              void* d_out, int out_size) {
    const int* x          = (const int*)d_in[0];
    const int* edge_index = (const int*)d_in[1];
    const int* edge_attr  = (const int*)d_in[2];
    const int* batch      = (const int*)d_in[3];
    const float* atom_emb  = (const float*)d_in[4];
    const float* vn_emb    = (const float*)d_in[5];
    const float* bond_emb  = (const float*)d_in[6];
    const float* conv_eps  = (const float*)d_in[7];
    const float* conv_W1   = (const float*)d_in[8];
    const float* conv_b1   = (const float*)d_in[9];
    const float* conv_bn_g = (const float*)d_in[10];
    const float* conv_bn_b = (const float*)d_in[11];
    const float* conv_bn_m = (const float*)d_in[12];
    const float* conv_bn_v = (const float*)d_in[13];
    const float* conv_W2   = (const float*)d_in[14];
    const float* conv_b2   = (const float*)d_in[15];
    const float* vn1_W  = (const float*)d_in[16];
    const float* vn1_b  = (const float*)d_in[17];
    const float* vn1_g  = (const float*)d_in[18];
    const float* vn1_be = (const float*)d_in[19];
    const float* vn1_m  = (const float*)d_in[20];
    const float* vn1_v  = (const float*)d_in[21];
    const float* vn2_W  = (const float*)d_in[22];
    const float* vn2_b  = (const float*)d_in[23];
    const float* vn2_g  = (const float*)d_in[24];
    const float* vn2_be = (const float*)d_in[25];
    const float* vn2_m  = (const float*)d_in[26];
    const float* vn2_v  = (const float*)d_in[27];
    const float* pW1 = (const float*)d_in[28];
    const float* pb1 = (const float*)d_in[29];
    const float* pW2 = (const float*)d_in[30];
    const float* pb2 = (const float*)d_in[31];
    float* out = (float*)d_out;

    float *h, *agg, *t, *vn, *pooled;
    __nv_bfloat16 *w0, *w1, *w2;
    __nv_bfloat16 *sZ0, *sZ1, *sZ2, *sT0, *sT1, *sT2;
    __nv_bfloat16 *sH0, *sH1, *sH2, *sV0, *sV1, *sV2, *sP0, *sP1, *sP2;
    cudaGetSymbolAddress((void**)&h, g_h);
    cudaGetSymbolAddress((void**)&agg, g_agg);
    cudaGetSymbolAddress((void**)&t, g_t);
    cudaGetSymbolAddress((void**)&vn, g_vn);
    cudaGetSymbolAddress((void**)&pooled, g_pooled);
    cudaGetSymbolAddress((void**)&w0, g_w0);
    cudaGetSymbolAddress((void**)&w1, g_w1);
    cudaGetSymbolAddress((void**)&w2, g_w2);
    cudaGetSymbolAddress((void**)&sZ0, g_Z0); cudaGetSymbolAddress((void**)&sZ1, g_Z1); cudaGetSymbolAddress((void**)&sZ2, g_Z2);
    cudaGetSymbolAddress((void**)&sT0, g_T0); cudaGetSymbolAddress((void**)&sT1, g_T1); cudaGetSymbolAddress((void**)&sT2, g_T2);
    cudaGetSymbolAddress((void**)&sH0, g_H0); cudaGetSymbolAddress((void**)&sH1, g_H1); cudaGetSymbolAddress((void**)&sH2, g_H2);
    cudaGetSymbolAddress((void**)&sV0, g_V0); cudaGetSymbolAddress((void**)&sV1, g_V1); cudaGetSymbolAddress((void**)&sV2, g_V2);
    cudaGetSymbolAddress((void**)&sP0, g_P0); cudaGetSymbolAddress((void**)&sP1, g_P1); cudaGetSymbolAddress((void**)&sP2, g_P2);

    const int OFF_W1 = 0;         // 128x256
    const int OFF_W2 = 32768;     // 256x128
    const int OFF_V1 = 65536;     // 256x256
    const int OFF_V2 = 131072;    // 256x128
    for (int i = 0; i < LAYERS; i++) {
        size_t off = (size_t)i * WT_L;
        wconv3_kernel<<<(H * H2 + 255) / 256, 256>>>(
            conv_W1 + (size_t)i * H * H2,
            w0 + off + OFF_W1, w1 + off + OFF_W1, w2 + off + OFF_W1, H * H2);
        wconv3_kernel<<<(H2 * H + 255) / 256, 256>>>(
            conv_W2 + (size_t)i * H2 * H,
            w0 + off + OFF_W2, w1 + off + OFF_W2, w2 + off + OFF_W2, H2 * H);
        wconv3_kernel<<<(H2 * H2 + 255) / 256, 256>>>(
            vn1_W + (size_t)i * H2 * H2,
            w0 + off + OFF_V1, w1 + off + OFF_V1, w2 + off + OFF_V1, H2 * H2);
        wconv3_kernel<<<(H2 * H + 255) / 256, 256>>>(
            vn2_W + (size_t)i * H2 * H,
            w0 + off + OFF_V2, w1 + off + OFF_V2, w2 + off + OFF_V2, H2 * H);
    }

    atom_kernel<<<(N_NODES * 32) / 256, 256>>>(x, atom_emb, h);
    vninit_kernel<<<(N_GRAPHS * 32) / 256, 256>>>(vn_emb, vn);
    split_plain_kernel<<<(N_GRAPHS * H / 4) / 256, 256>>>(vn, sV0, sV1, sV2);

    for (int i = 0; i < LAYERS; i++) {
        size_t off = (size_t)i * WT_L;
        addvn_kernel<<<(N_NODES * 32) / 256, 256>>>(h, vn, batch, agg);
        edge_kernel<<<N_EDGES / 8, 256>>>(edge_index, edge_attr,
                                          bond_emb + (size_t)i * FB * VB * H, h, agg);
        // z = (1+eps)h + agg  -> bf16x3
        split_z_kernel<<<(N_NODES * H / 4) / 256, 256>>>(h, agg, conv_eps + i, sZ0, sZ1, sZ2);
        // conv1: T(splits) = relu(bn(z @ W1 + b1))   [N,256]
        gemm3<0, true, false, true><<<dim3(N_NODES / 128, 4), 256>>>(
            sZ0, sZ1, sZ2, nullptr, nullptr, nullptr, nullptr,
            w0 + off + OFF_W1, w1 + off + OFF_W1, w2 + off + OFF_W1,
            conv_b1 + i * H2, conv_bn_g + i * H2, conv_bn_b + i * H2,
            conv_bn_m + i * H2, conv_bn_v + i * H2,
            nullptr, sT0, sT1, sT2, N_NODES, H, H2);
        // conv2: h = T @ W2 + b2  (emit f32 h + splits sH)  [N,128]
        gemm3<0, false, true, true><<<dim3(N_NODES / 128, 2), 256>>>(
            sT0, sT1, sT2, nullptr, nullptr, nullptr, nullptr,
            w0 + off + OFF_W2, w1 + off + OFF_W2, w2 + off + OFF_W2,
            conv_b2 + i * H, nullptr, nullptr, nullptr, nullptr,
            h, sH0, sH1, sH2, N_NODES, H2, H);
        // vn1: t = relu(bn(concat(vn[batch], h) @ V1 + b))  [N,256] (f32 only)
        gemm3<2, true, true, false><<<dim3(N_NODES / 128, 4), 256>>>(
            sH0, sH1, sH2, sV0, sV1, sV2, batch,
            w0 + off + OFF_V1, w1 + off + OFF_V1, w2 + off + OFF_V1,
            vn1_b + i * H2, vn1_g + i * H2, vn1_be + i * H2,
            vn1_m + i * H2, vn1_v + i * H2,
            t, nullptr, nullptr, nullptr, N_NODES, H2, H2);
        zero_pooled_kernel<<<(N_GRAPHS * H2 / 4) / 256, 256>>>((float4*)pooled);
        pool_kernel<<<(N_NODES * 64) / 256, 256>>>(t, batch, pooled);
        split_plain_kernel<<<(N_GRAPHS * H2 / 4) / 256, 256>>>(pooled, sP0, sP1, sP2);
        // vn2: vn = relu(bn(pooled @ V2 + b))  (emit f32 vn + splits sV)  [G,128]
        gemm3<0, true, true, true><<<dim3(N_GRAPHS / 128, 2), 256>>>(
            sP0, sP1, sP2, nullptr, nullptr, nullptr, nullptr,
            w0 + off + OFF_V2, w1 + off + OFF_V2, w2 + off + OFF_V2,
            vn2_b + i * H, vn2_g + i * H, vn2_be + i * H,
            vn2_m + i * H, vn2_v + i * H,
            vn, sV0, sV1, sV2, N_GRAPHS, H2, H);
    }
    final_kernel<<<N_GRAPHS, 128>>>(vn, pW1, pb1, pW2, pb2, out);
}

// round 12
// speedup vs baseline: 1.6104x; 1.3102x over previous
#include <cuda_runtime.h>
#include <cuda_bf16.h>
#include <mma.h>

using namespace nvcuda;

#define N_NODES 262144
#define N_EDGES 1048576
#define N_GRAPHS 8192
#define H 128
#define H2 256
#define LAYERS 4
#define FA 9
#define VA 64
#define FB 3
#define VB 8

// ---------------- scratch ----------------------------------------------------
__device__ float g_h[(size_t)N_NODES * H];
__device__ float g_agg[(size_t)N_NODES * H];
__device__ float g_t[(size_t)N_NODES * H2];
__device__ float g_vn[(size_t)N_GRAPHS * H];
__device__ float g_pooled[(size_t)N_GRAPHS * H2];
// bf16x2 weights [K][N]
#define WT_L (32768 + 32768 + 65536 + 32768)   // 163840 per layer
__device__ __nv_bfloat16 g_w0[(size_t)LAYERS * WT_L];
__device__ __nv_bfloat16 g_w1[(size_t)LAYERS * WT_L];
// bf16x2 activation scratch
__device__ __nv_bfloat16 g_Z0[(size_t)N_NODES * H],  g_Z1[(size_t)N_NODES * H];
__device__ __nv_bfloat16 g_T0[(size_t)N_NODES * H2], g_T1[(size_t)N_NODES * H2];
__device__ __nv_bfloat16 g_H0[(size_t)N_NODES * H],  g_H1[(size_t)N_NODES * H];
__device__ __nv_bfloat16 g_V0[(size_t)N_GRAPHS * H], g_V1[(size_t)N_GRAPHS * H];
__device__ __nv_bfloat16 g_P0[(size_t)N_GRAPHS * H2],g_P1[(size_t)N_GRAPHS * H2];

__device__ __forceinline__ void split2(float v, __nv_bfloat16& o0, __nv_bfloat16& o1) {
    o0 = __float2bfloat16(v);
    o1 = __float2bfloat16(v - __bfloat162float(o0));
}

__device__ __forceinline__ void cp16(void* dst, const void* src) {
    unsigned d = (unsigned)__cvta_generic_to_shared(dst);
    asm volatile("cp.async.cg.shared.global [%0], [%1], 16;\n" :: "r"(d), "l"(src));
}

// ---- bf16x2 weight split ------------------------------------------------------
__global__ void wconv2_kernel(const float* __restrict__ W,
                              __nv_bfloat16* __restrict__ W0,
                              __nv_bfloat16* __restrict__ W1, int total) {
    int idx = blockIdx.x * blockDim.x + threadIdx.x;
    if (idx >= total) return;
    split2(W[idx], W0[idx], W1[idx]);
}

// ---- elementwise split of an f32 array -----------------------------------------
__global__ void split_plain_kernel(const float* __restrict__ src,
                                   __nv_bfloat16* __restrict__ D0,
                                   __nv_bfloat16* __restrict__ D1) {
    int idx = blockIdx.x * blockDim.x + threadIdx.x;   // total/4 threads
    float4 v = *(const float4*)(src + (size_t)idx * 4);
    __nv_bfloat16 a0[4], a1[4];
    split2(v.x, a0[0], a1[0]);
    split2(v.y, a0[1], a1[1]);
    split2(v.z, a0[2], a1[2]);
    split2(v.w, a0[3], a1[3]);
    *(uint2*)(D0 + (size_t)idx * 4) = *(uint2*)a0;
    *(uint2*)(D1 + (size_t)idx * 4) = *(uint2*)a1;
}

// ---- z = (1+eps)h + agg, split to bf16x2 ---------------------------------------
__global__ void split_z_kernel(const float* __restrict__ h,
                               const float* __restrict__ agg,
                               const float* __restrict__ epsp,
                               __nv_bfloat16* __restrict__ Z0,
                               __nv_bfloat16* __restrict__ Z1) {
    int idx = blockIdx.x * blockDim.x + threadIdx.x;   // N*H/4 threads
    float c0 = 1.0f + __ldg(epsp);
    float4 hv = *(const float4*)(h + (size_t)idx * 4);
    float4 gv = *(const float4*)(agg + (size_t)idx * 4);
    float z[4] = { fmaf(c0, hv.x, gv.x), fmaf(c0, hv.y, gv.y),
                   fmaf(c0, hv.z, gv.z), fmaf(c0, hv.w, gv.w) };
    __nv_bfloat16 a0[4], a1[4];
#pragma unroll
    for (int q = 0; q < 4; q++) split2(z[q], a0[q], a1[q]);
    *(uint2*)(Z0 + (size_t)idx * 4) = *(uint2*)a0;
    *(uint2*)(Z1 + (size_t)idx * 4) = *(uint2*)a1;
}

// ---------------- atom encoder ---------------------------------------------------
__global__ void atom_kernel(const int* __restrict__ x,
                            const float* __restrict__ emb,
                            float* __restrict__ h) {
    int idx = blockIdx.x * blockDim.x + threadIdx.x;
    int n = idx >> 5;
    int c = (idx & 31) << 2;
    float4 acc = make_float4(0.f, 0.f, 0.f, 0.f);
#pragma unroll
    for (int f = 0; f < FA; f++) {
        int v = x[n * FA + f];
        float4 e = *(const float4*)(emb + ((size_t)(f * VA + v) * H) + c);
        acc.x += e.x; acc.y += e.y; acc.z += e.z; acc.w += e.w;
    }
    *(float4*)(h + (size_t)n * H + c) = acc;
}

__global__ void vninit_kernel(const float* __restrict__ vn_emb,
                              float* __restrict__ vn) {
    int idx = blockIdx.x * blockDim.x + threadIdx.x;
    int g = idx >> 5;
    int c = (idx & 31) << 2;
    *(float4*)(vn + (size_t)g * H + c) = *(const float4*)(vn_emb + c);
}

__global__ void addvn_kernel(float* __restrict__ h,
                             const float* __restrict__ vn,
                             const int* __restrict__ batch,
                             float* __restrict__ agg) {
    int idx = blockIdx.x * blockDim.x + threadIdx.x;
    int n = idx >> 5;
    int c = (idx & 31) << 2;
    int g = batch[n];
    float4 hv = *(float4*)(h + (size_t)n * H + c);
    float4 vv = *(const float4*)(vn + (size_t)g * H + c);
    hv.x += vv.x; hv.y += vv.y; hv.z += vv.z; hv.w += vv.w;
    *(float4*)(h + (size_t)n * H + c) = hv;
    *(float4*)(agg + (size_t)n * H + c) = make_float4(0.f, 0.f, 0.f, 0.f);
}

__global__ void edge_kernel(const int* __restrict__ ei,
                            const int* __restrict__ ea,
                            const float* __restrict__ bond,
                            const float* __restrict__ h,
                            float* __restrict__ agg) {
    __shared__ float tab[FB * VB * H];
    for (int i = threadIdx.x; i < FB * VB * H; i += blockDim.x) tab[i] = bond[i];
    __syncthreads();
    int e = (blockIdx.x * blockDim.x + threadIdx.x) >> 5;
    int lane = threadIdx.x & 31;
    int src = ei[e];
    int dst = ei[N_EDGES + e];
    int a0 = ea[e * 3 + 0], a1 = ea[e * 3 + 1], a2 = ea[e * 3 + 2];
    int c = lane << 2;
    float4 hv = *(const float4*)(h + (size_t)src * H + c);
    float4 e0 = *(const float4*)(tab + (0 * VB + a0) * H + c);
    float4 e1 = *(const float4*)(tab + (1 * VB + a1) * H + c);
    float4 e2 = *(const float4*)(tab + (2 * VB + a2) * H + c);
    float m0 = fmaxf(hv.x + e0.x + e1.x + e2.x, 0.f);
    float m1 = fmaxf(hv.y + e0.y + e1.y + e2.y, 0.f);
    float m2 = fmaxf(hv.z + e0.z + e1.z + e2.z, 0.f);
    float m3 = fmaxf(hv.w + e0.w + e1.w + e2.w, 0.f);
    float* p = agg + (size_t)dst * H + c;
    atomicAdd(p + 0, m0);
    atomicAdd(p + 1, m1);
    atomicAdd(p + 2, m2);
    atomicAdd(p + 3, m3);
}

// ======== bf16x2 GEMM v4: 3 products, BK=32, conflict-free, double-buffered =====
// Tile 128M x 64N. 8 warps = 4m x 2n, warp tile 32x32.
// MODE_A: 0 = A from (A0g,A1g)[M,K]; 2 = concat(V[batch][G,128], A[M,128]).
#define BK 32
#define A_LD 40
#define B_LD 72
#define OFF_A0 0
#define OFF_A1 10240
#define OFF_B0 20480
#define OFF_B1 25088
#define STAGE  29696   // bytes per stage; x2 = 59392 (dynamic SMEM)

template <int MODE_A, bool BN_RELU, bool OUT_F32, bool OUT_SPLIT>
__global__ __launch_bounds__(256, 2) void gemm3(
    const __nv_bfloat16* __restrict__ A0g, const __nv_bfloat16* __restrict__ A1g,
    const __nv_bfloat16* __restrict__ V0g, const __nv_bfloat16* __restrict__ V1g,
    const int* __restrict__ batch,
    const __nv_bfloat16* __restrict__ W0, const __nv_bfloat16* __restrict__ W1,
    const float* __restrict__ bias,
    const float* __restrict__ bng, const float* __restrict__ bnb,
    const float* __restrict__ bnm, const float* __restrict__ bnv,
    float* __restrict__ Cf,
    __nv_bfloat16* __restrict__ C0, __nv_bfloat16* __restrict__ C1,
    int M, int K, int Ncol) {
    extern __shared__ __align__(16) char smem[];

    const int tid = threadIdx.x;
    const int wid = tid >> 5;
    const int wm = wid & 3;
    const int wn = wid >> 2;
    const int m0 = blockIdx.x * 128;
    const int n0 = blockIdx.y * 64;

    const int arow = tid >> 1;               // 0..127
    const int ak = (tid & 1) << 4;           // 0 or 16
    const int grow = m0 + arow;
    int bg = 0;
    if (MODE_A == 2) bg = batch[grow];

    wmma::fragment<wmma::accumulator, 16, 16, 16, float> acc0[2][2], accR[2][2];
#pragma unroll
    for (int mi = 0; mi < 2; mi++)
#pragma unroll
        for (int ni = 0; ni < 2; ni++) {
            wmma::fill_fragment(acc0[mi][ni], 0.0f);
            wmma::fill_fragment(accR[mi][ni], 0.0f);
        }

    auto stage = [&](int kt, int buf) {
        char* base = smem + buf * STAGE;
        int gk = kt * BK + ak;
        const __nv_bfloat16 *s0, *s1;
        if (MODE_A == 0) {
            size_t o = (size_t)grow * K + gk;
            s0 = A0g + o; s1 = A1g + o;
        } else {
            if (gk < H) {
                size_t o = (size_t)bg * H + gk;
                s0 = V0g + o; s1 = V1g + o;
            } else {
                size_t o = (size_t)grow * H + (gk - H);
                s0 = A0g + o; s1 = A1g + o;
            }
        }
        int soff = (arow * A_LD + ak) * 2;
        cp16(base + OFF_A0 + soff, s0);
        cp16(base + OFF_A0 + soff + 16, s0 + 8);
        cp16(base + OFF_A1 + soff, s1);
        cp16(base + OFF_A1 + soff + 16, s1 + 8);
        // B: 2 splits x 32 rows x 64 cols = 512 16B-chunks, 2 per thread
#pragma unroll
        for (int c = tid; c < 512; c += 256) {
            int sp = c >> 8, rem = c & 255, r = rem >> 3, ch = rem & 7;
            size_t go = (size_t)(kt * BK + r) * Ncol + n0 + ch * 8;
            const __nv_bfloat16* src = (sp == 0) ? (W0 + go) : (W1 + go);
            cp16(base + OFF_B0 + sp * 4608 + (r * B_LD + ch * 8) * 2, src);
        }
        asm volatile("cp.async.commit_group;\n" ::);
    };

    const int KT = K / BK;
    stage(0, 0);
    for (int kt = 0; kt < KT; kt++) {
        if (kt + 1 < KT) {
            stage(kt + 1, (kt + 1) & 1);
            asm volatile("cp.async.wait_group 1;\n" ::);
        } else {
            asm volatile("cp.async.wait_group 0;\n" ::);
        }
        __syncthreads();
        char* base = smem + (kt & 1) * STAGE;
        const __nv_bfloat16* Ab0 = (const __nv_bfloat16*)(base + OFF_A0);
        const __nv_bfloat16* Ab1 = (const __nv_bfloat16*)(base + OFF_A1);
        const __nv_bfloat16* Bb0 = (const __nv_bfloat16*)(base + OFF_B0);
        const __nv_bfloat16* Bb1 = (const __nv_bfloat16*)(base + OFF_B1);

#pragma unroll
        for (int kk = 0; kk < 2; kk++) {
            wmma::fragment<wmma::matrix_a, 16, 16, 16, __nv_bfloat16, wmma::row_major>
                a0[2], a1[2];
#pragma unroll
            for (int mi = 0; mi < 2; mi++) {
                int ao = (wm * 32 + mi * 16) * A_LD + kk * 16;
                wmma::load_matrix_sync(a0[mi], Ab0 + ao, A_LD);
                wmma::load_matrix_sync(a1[mi], Ab1 + ao, A_LD);
            }
#pragma unroll
            for (int ni = 0; ni < 2; ni++) {
                wmma::fragment<wmma::matrix_b, 16, 16, 16, __nv_bfloat16, wmma::row_major> b0, b1;
                int bo = (kk * 16) * B_LD + wn * 32 + ni * 16;
                wmma::load_matrix_sync(b0, Bb0 + bo, B_LD);
                wmma::load_matrix_sync(b1, Bb1 + bo, B_LD);
#pragma unroll
                for (int mi = 0; mi < 2; mi++) {
                    wmma::mma_sync(acc0[mi][ni], a0[mi], b0, acc0[mi][ni]);
                    wmma::mma_sync(accR[mi][ni], a0[mi], b1, accR[mi][ni]);
                    wmma::mma_sync(accR[mi][ni], a1[mi], b0, accR[mi][ni]);
                }
            }
        }
        __syncthreads();
    }

    // park combined result in SMEM (aliases stage buffers; all reads done)
    float* Cs = (float*)smem;
#pragma unroll
    for (int mi = 0; mi < 2; mi++)
#pragma unroll
        for (int ni = 0; ni < 2; ni++) {
#pragma unroll
            for (int e = 0; e < acc0[mi][ni].num_elements; e++)
                acc0[mi][ni].x[e] += accR[mi][ni].x[e];
            wmma::store_matrix_sync(&Cs[(wm * 32 + mi * 16) * 64 + wn * 32 + ni * 16],
                                    acc0[mi][ni], 64, wmma::mem_row_major);
        }
    __syncthreads();

    const int erow = tid >> 1;
    const int ecb = (tid & 1) << 5;
    const size_t rowoff = (size_t)(m0 + erow) * Ncol;
#pragma unroll
    for (int j = 0; j < 32; j += 4) {
        float y[4];
#pragma unroll
        for (int q = 0; q < 4; q++) {
            int col = n0 + ecb + j + q;
            float v = Cs[erow * 64 + ecb + j + q];
            if (BN_RELU) {
                float s = __ldg(bng + col) * rsqrtf(__ldg(bnv + col) + 1e-5f);
                float off = (__ldg(bias + col) - __ldg(bnm + col)) * s + __ldg(bnb + col);
                y[q] = fmaxf(fmaf(v, s, off), 0.0f);
            } else {
                y[q] = v + __ldg(bias + col);
            }
        }
        size_t o = rowoff + n0 + ecb + j;
        if (OUT_F32)
            *(float4*)(Cf + o) = make_float4(y[0], y[1], y[2], y[3]);
        if (OUT_SPLIT) {
            __nv_bfloat16 s0[4], s1[4];
#pragma unroll
            for (int q = 0; q < 4; q++) split2(y[q], s0[q], s1[q]);
            *(uint2*)(C0 + o) = *(uint2*)s0;
            *(uint2*)(C1 + o) = *(uint2*)s1;
        }
    }
}

// ---------------- zero pooled -----------------------------------------------------
__global__ void zero_pooled_kernel(float4* __restrict__ p) {
    int idx = blockIdx.x * blockDim.x + threadIdx.x;
    p[idx] = make_float4(0.f, 0.f, 0.f, 0.f);
}

__global__ void pool_kernel(const float* __restrict__ t,
                            const int* __restrict__ batch,
                            float* __restrict__ pooled) {
    int idx = blockIdx.x * blockDim.x + threadIdx.x;
    int n = idx >> 6;
    int c = (idx & 63) << 2;
    int g = batch[n];
    float4 v = *(const float4*)(t + (size_t)n * H2 + c);
    float* p = pooled + (size_t)g * H2 + c;
    atomicAdd(p + 0, v.x);
    atomicAdd(p + 1, v.y);
    atomicAdd(p + 2, v.z);
    atomicAdd(p + 3, v.w);
}

__global__ void final_kernel(const float* __restrict__ vn,
                             const float* __restrict__ pW1,
                             const float* __restrict__ pb1,
                             const float* __restrict__ pW2,
                             const float* __restrict__ pb2,
                             float* __restrict__ out) {
    int g = blockIdx.x;
    int j = threadIdx.x;
    __shared__ float vrow[H];
    vrow[j] = vn[(size_t)g * H + j];
    __syncthreads();
    float acc = pb1[j];
#pragma unroll 8
    for (int k = 0; k < H; k++) acc = fmaf(vrow[k], __ldg(pW1 + k * H + j), acc);
    float val = fmaxf(acc, 0.0f) * __ldg(pW2 + j);
#pragma unroll
    for (int o = 16; o > 0; o >>= 1) val += __shfl_down_sync(0xffffffffu, val, o);
    __shared__ float part[4];
    if ((j & 31) == 0) part[j >> 5] = val;
    __syncthreads();
    if (j == 0) {
        float s = part[0] + part[1] + part[2] + part[3] + pb2[0];
        out[g] = fminf(fmaxf(s, 0.0f), 50.0f);
    }
}

// ---------------- launch -------------------------------------------------------------
extern "C" void kernel_launch(void* const* d_in, const int* in_sizes, int n_in,
                              void* d_out, int out_size) {
    const int* x          = (const int*)d_in[0];
    const int* edge_index = (const int*)d_in[1];
    const int* edge_attr  = (const int*)d_in[2];
    const int* batch      = (const int*)d_in[3];
    const float* atom_emb  = (const float*)d_in[4];
    const float* vn_emb    = (const float*)d_in[5];
    const float* bond_emb  = (const float*)d_in[6];
    const float* conv_eps  = (const float*)d_in[7];
    const float* conv_W1   = (const float*)d_in[8];
    const float* conv_b1   = (const float*)d_in[9];
    const float* conv_bn_g = (const float*)d_in[10];
    const float* conv_bn_b = (const float*)d_in[11];
    const float* conv_bn_m = (const float*)d_in[12];
    const float* conv_bn_v = (const float*)d_in[13];
    const float* conv_W2   = (const float*)d_in[14];
    const float* conv_b2   = (const float*)d_in[15];
    const float* vn1_W  = (const float*)d_in[16];
    const float* vn1_b  = (const float*)d_in[17];
    const float* vn1_g  = (const float*)d_in[18];
    const float* vn1_be = (const float*)d_in[19];
    const float* vn1_m  = (const float*)d_in[20];
    const float* vn1_v  = (const float*)d_in[21];
    const float* vn2_W  = (const float*)d_in[22];
    const float* vn2_b  = (const float*)d_in[23];
    const float* vn2_g  = (const float*)d_in[24];
    const float* vn2_be = (const float*)d_in[25];
    const float* vn2_m  = (const float*)d_in[26];
    const float* vn2_v  = (const float*)d_in[27];
    const float* pW1 = (const float*)d_in[28];
    const float* pb1 = (const float*)d_in[29];
    const float* pW2 = (const float*)d_in[30];
    const float* pb2 = (const float*)d_in[31];
    float* out = (float*)d_out;

    float *h, *agg, *t, *vn, *pooled;
    __nv_bfloat16 *w0, *w1;
    __nv_bfloat16 *sZ0, *sZ1, *sT0, *sT1, *sH0, *sH1, *sV0, *sV1, *sP0, *sP1;
    cudaGetSymbolAddress((void**)&h, g_h);
    cudaGetSymbolAddress((void**)&agg, g_agg);
    cudaGetSymbolAddress((void**)&t, g_t);
    cudaGetSymbolAddress((void**)&vn, g_vn);
    cudaGetSymbolAddress((void**)&pooled, g_pooled);
    cudaGetSymbolAddress((void**)&w0, g_w0);
    cudaGetSymbolAddress((void**)&w1, g_w1);
    cudaGetSymbolAddress((void**)&sZ0, g_Z0); cudaGetSymbolAddress((void**)&sZ1, g_Z1);
    cudaGetSymbolAddress((void**)&sT0, g_T0); cudaGetSymbolAddress((void**)&sT1, g_T1);
    cudaGetSymbolAddress((void**)&sH0, g_H0); cudaGetSymbolAddress((void**)&sH1, g_H1);
    cudaGetSymbolAddress((void**)&sV0, g_V0); cudaGetSymbolAddress((void**)&sV1, g_V1);
    cudaGetSymbolAddress((void**)&sP0, g_P0); cudaGetSymbolAddress((void**)&sP1, g_P1);

    // opt-in dynamic SMEM (59392 bytes) for the 4 gemm3 instantiations
    const int DSM = 2 * STAGE;
    cudaFuncSetAttribute(gemm3<0, true,  false, true >, cudaFuncAttributeMaxDynamicSharedMemorySize, DSM);
    cudaFuncSetAttribute(gemm3<0, false, true,  true >, cudaFuncAttributeMaxDynamicSharedMemorySize, DSM);
    cudaFuncSetAttribute(gemm3<2, true,  true,  false>, cudaFuncAttributeMaxDynamicSharedMemorySize, DSM);
    cudaFuncSetAttribute(gemm3<0, true,  true,  true >, cudaFuncAttributeMaxDynamicSharedMemorySize, DSM);

    const int OFF_W1 = 0;         // 128x256
    const int OFF_W2 = 32768;     // 256x128
    const int OFF_V1 = 65536;     // 256x256
    const int OFF_V2 = 131072;    // 256x128
    for (int i = 0; i < LAYERS; i++) {
        size_t off = (size_t)i * WT_L;
        wconv2_kernel<<<(H * H2 + 255) / 256, 256>>>(
            conv_W1 + (size_t)i * H * H2, w0 + off + OFF_W1, w1 + off + OFF_W1, H * H2);
        wconv2_kernel<<<(H2 * H + 255) / 256, 256>>>(
            conv_W2 + (size_t)i * H2 * H, w0 + off + OFF_W2, w1 + off + OFF_W2, H2 * H);
        wconv2_kernel<<<(H2 * H2 + 255) / 256, 256>>>(
            vn1_W + (size_t)i * H2 * H2, w0 + off + OFF_V1, w1 + off + OFF_V1, H2 * H2);
        wconv2_kernel<<<(H2 * H + 255) / 256, 256>>>(
            vn2_W + (size_t)i * H2 * H, w0 + off + OFF_V2, w1 + off + OFF_V2, H2 * H);
    }

    atom_kernel<<<(N_NODES * 32) / 256, 256>>>(x, atom_emb, h);
    vninit_kernel<<<(N_GRAPHS * 32) / 256, 256>>>(vn_emb, vn);
    split_plain_kernel<<<(N_GRAPHS * H / 4) / 256, 256>>>(vn, sV0, sV1);

    for (int i = 0; i < LAYERS; i++) {
        size_t off = (size_t)i * WT_L;
        addvn_kernel<<<(N_NODES * 32) / 256, 256>>>(h, vn, batch, agg);
        edge_kernel<<<N_EDGES / 8, 256>>>(edge_index, edge_attr,
                                          bond_emb + (size_t)i * FB * VB * H, h, agg);
        // z = (1+eps)h + agg  -> bf16x2
        split_z_kernel<<<(N_NODES * H / 4) / 256, 256>>>(h, agg, conv_eps + i, sZ0, sZ1);
        // conv1: T(splits) = relu(bn(z @ W1 + b1))   [N,256]
        gemm3<0, true, false, true><<<dim3(N_NODES / 128, 4), 256, DSM>>>(
            sZ0, sZ1, nullptr, nullptr, nullptr,
            w0 + off + OFF_W1, w1 + off + OFF_W1,
            conv_b1 + i * H2, conv_bn_g + i * H2, conv_bn_b + i * H2,
            conv_bn_m + i * H2, conv_bn_v + i * H2,
            nullptr, sT0, sT1, N_NODES, H, H2);
        // conv2: h = T @ W2 + b2  (emit f32 h + splits sH)  [N,128]
        gemm3<0, false, true, true><<<dim3(N_NODES / 128, 2), 256, DSM>>>(
            sT0, sT1, nullptr, nullptr, nullptr,
            w0 + off + OFF_W2, w1 + off + OFF_W2,
            conv_b2 + i * H, nullptr, nullptr, nullptr, nullptr,
            h, sH0, sH1, N_NODES, H2, H);
        // vn1: t = relu(bn(concat(vn[batch], h) @ V1 + b))  [N,256] (f32 only)
        gemm3<2, true, true, false><<<dim3(N_NODES / 128, 4), 256, DSM>>>(
            sH0, sH1, sV0, sV1, batch,
            w0 + off + OFF_V1, w1 + off + OFF_V1,
            vn1_b + i * H2, vn1_g + i * H2, vn1_be + i * H2,
            vn1_m + i * H2, vn1_v + i * H2,
            t, nullptr, nullptr, N_NODES, H2, H2);
        zero_pooled_kernel<<<(N_GRAPHS * H2 / 4) / 256, 256>>>((float4*)pooled);
        pool_kernel<<<(N_NODES * 64) / 256, 256>>>(t, batch, pooled);
        split_plain_kernel<<<(N_GRAPHS * H2 / 4) / 256, 256>>>(pooled, sP0, sP1);
        // vn2: vn = relu(bn(pooled @ V2 + b))  (emit f32 vn + splits sV)  [G,128]
        gemm3<0, true, true, true><<<dim3(N_GRAPHS / 128, 2), 256, DSM>>>(
            sP0, sP1, nullptr, nullptr, nullptr,
            w0 + off + OFF_V2, w1 + off + OFF_V2,
            vn2_b + i * H, vn2_g + i * H, vn2_be + i * H,
            vn2_m + i * H, vn2_v + i * H,
            vn, sV0, sV1, N_GRAPHS, H2, H);
    }
    final_kernel<<<N_GRAPHS, 128>>>(vn, pW1, pb1, pW2, pb2, out);
}